// round 1
// baseline (speedup 1.0000x reference)
#include <cuda_runtime.h>

#define BB 4
#define LL 2048
#define DD 1024
#define HH 16
#define DKK 64
#define NROWS (BB*LL)

// Scratch (allocation-free rule: __device__ globals)
__device__ float g_qkv[(size_t)NROWS * 3 * DD];   // [8192, 3072] : Q|K|V
__device__ float g_ctx[(size_t)NROWS * DD];       // [8192, 1024]

__device__ __forceinline__ float fexp2(float x) {
    float y; asm("ex2.approx.ftz.f32 %0, %1;" : "=f"(y) : "f"(x)); return y;
}

// ---------------------------------------------------------------------------
// SGEMM: C = A(M,K) @ W(K,N) + bias   (row-major; M%128==0, N%128==0, K%8==0)
// 128x128 tile, BK=8, 256 threads, 8x8 micro-tile, register prefetch.
// ---------------------------------------------------------------------------
__global__ __launch_bounds__(256, 2)
void sgemm_bias(const float* __restrict__ A, const float* __restrict__ W,
                const float* __restrict__ bias, float* __restrict__ C,
                int M, int N, int K)
{
    __shared__ __align__(16) float As[8][132];   // [k][row] transposed
    __shared__ __align__(16) float Bs[8][132];   // [k][col]

    const int tid = threadIdx.x;
    const int tx  = tid & 15;        // col group
    const int ty  = tid >> 4;        // row group
    const int row0 = blockIdx.y * 128;
    const int col0 = blockIdx.x * 128;

    const int ar = tid >> 1;         // 0..127
    const int ac = (tid & 1) << 2;   // 0 or 4
    const int br = tid >> 5;         // 0..7
    const int bc = (tid & 31) << 2;  // 0..124

    const float* Aptr = A + (size_t)(row0 + ar) * K + ac;
    const float* Wptr = W + (size_t)br * N + col0 + bc;

    float4 av = *(const float4*)Aptr;
    float4 bv = *(const float4*)Wptr;

    float acc[8][8];
    #pragma unroll
    for (int i = 0; i < 8; i++)
        #pragma unroll
        for (int j = 0; j < 8; j++) acc[i][j] = 0.0f;

    for (int kt = 0; kt < K; kt += 8) {
        __syncthreads();
        As[ac+0][ar] = av.x; As[ac+1][ar] = av.y;
        As[ac+2][ar] = av.z; As[ac+3][ar] = av.w;
        *(float4*)&Bs[br][bc] = bv;
        __syncthreads();
        if (kt + 8 < K) {
            av = *(const float4*)(Aptr + kt + 8);
            bv = *(const float4*)(Wptr + (size_t)(kt + 8) * N);
        }
        #pragma unroll
        for (int k = 0; k < 8; k++) {
            float4 a0 = *(const float4*)&As[k][ty*8];
            float4 a1 = *(const float4*)&As[k][ty*8+4];
            float4 b0 = *(const float4*)&Bs[k][tx*4];        // cols 4tx..4tx+3
            float4 b1 = *(const float4*)&Bs[k][64 + tx*4];   // cols 64+4tx..
            float ra[8] = {a0.x,a0.y,a0.z,a0.w,a1.x,a1.y,a1.z,a1.w};
            float rb[8] = {b0.x,b0.y,b0.z,b0.w,b1.x,b1.y,b1.z,b1.w};
            #pragma unroll
            for (int i = 0; i < 8; i++)
                #pragma unroll
                for (int j = 0; j < 8; j++)
                    acc[i][j] += ra[i] * rb[j];
        }
    }

    float4 bias0 = *(const float4*)&bias[col0 + tx*4];
    float4 bias1 = *(const float4*)&bias[col0 + 64 + tx*4];
    #pragma unroll
    for (int i = 0; i < 8; i++) {
        float* crow = C + (size_t)(row0 + ty*8 + i) * N + col0;
        float4 v0 = {acc[i][0]+bias0.x, acc[i][1]+bias0.y,
                     acc[i][2]+bias0.z, acc[i][3]+bias0.w};
        float4 v1 = {acc[i][4]+bias1.x, acc[i][5]+bias1.y,
                     acc[i][6]+bias1.z, acc[i][7]+bias1.w};
        *(float4*)&crow[tx*4]      = v0;
        *(float4*)&crow[64 + tx*4] = v1;
    }
}

// ---------------------------------------------------------------------------
// Fused masked attention (flash-style, fp32).
// Block: 256 threads = 16 ty (8 rows each) x 16 tx (4 cols each).
// BM=128 queries, BN=64 keys/iter, DK=64.
// Mask semantics: masked score -> exactly 0.0, included in row max and in the
// softmax denominator; attention weight then zeroed for PV.
// Softmax in log2 domain (fold 1/8 * log2e into score scale).
// ---------------------------------------------------------------------------
#define ATTN_SMEM_FLOATS (64*132 + 64*68 + 64*68 + 64*132)

__global__ __launch_bounds__(256, 1)
void attn_kernel(const float* __restrict__ qkv, const int* __restrict__ mask,
                 float* __restrict__ ctx)
{
    extern __shared__ __align__(16) float smem[];
    float (*Qs)[132] = (float(*)[132])(smem);                        // [d][row]
    float (*Ks)[68]  = (float(*)[68]) (smem + 64*132);               // [d][key]
    float (*Vs)[68]  = (float(*)[68]) (smem + 64*132 + 64*68);       // [key][d]
    float (*Ps)[132] = (float(*)[132])(smem + 64*132 + 2*64*68);     // [key][row]

    const int tid = threadIdx.x;
    const int tx  = tid & 15;
    const int ty  = tid >> 4;
    const int b   = blockIdx.y >> 4;
    const int h   = blockIdx.y & 15;
    const int q0  = blockIdx.x * 128;

    const size_t rowbase = (size_t)b * LL;
    const float* qb = qkv + rowbase * (3*DD) + h * DKK;
    const float* kb = qb + DD;
    const float* vb = qb + 2*DD;
    const int*   mb = mask + (size_t)b * LL * LL;

    // Load Q tile [128 rows x 64 dims], store transposed Qs[d][r]
    #pragma unroll
    for (int it = 0; it < 8; it++) {
        int idx = it*256 + tid;
        int r   = idx >> 4;
        int d4  = (idx & 15) << 2;
        float4 v = *(const float4*)(qb + (size_t)(q0 + r)*(3*DD) + d4);
        Qs[d4+0][r] = v.x; Qs[d4+1][r] = v.y; Qs[d4+2][r] = v.z; Qs[d4+3][r] = v.w;
    }

    float o[8][4];
    float mi[8], li[8];
    #pragma unroll
    for (int i = 0; i < 8; i++) {
        mi[i] = -1e30f; li[i] = 0.0f;
        #pragma unroll
        for (int j = 0; j < 4; j++) o[i][j] = 0.0f;
    }

    const float cs = 0.18033688011112042f;  // log2(e) / sqrt(64)

    for (int t = 0; t < LL/64; t++) {
        const int k0 = t * 64;
        __syncthreads();   // protect Ks/Vs/Ps against previous-iter readers
        #pragma unroll
        for (int it = 0; it < 4; it++) {
            int idx = it*256 + tid;
            int r   = idx >> 4;
            int d4  = (idx & 15) << 2;
            float4 kv = *(const float4*)(kb + (size_t)(k0 + r)*(3*DD) + d4);
            Ks[d4+0][r] = kv.x; Ks[d4+1][r] = kv.y; Ks[d4+2][r] = kv.z; Ks[d4+3][r] = kv.w;
            float4 vv = *(const float4*)(vb + (size_t)(k0 + r)*(3*DD) + d4);
            *(float4*)&Vs[r][d4] = vv;
        }
        __syncthreads();

        // S = Q @ K^T (tile 128x64); thread: rows ty*8+i, keys tx*4+j
        float s[8][4];
        #pragma unroll
        for (int i = 0; i < 8; i++)
            #pragma unroll
            for (int j = 0; j < 4; j++) s[i][j] = 0.0f;

        #pragma unroll 8
        for (int d = 0; d < 64; d++) {
            float4 qa = *(const float4*)&Qs[d][ty*8];
            float4 qbv = *(const float4*)&Qs[d][ty*8+4];
            float4 kf = *(const float4*)&Ks[d][tx*4];
            float rq[8] = {qa.x,qa.y,qa.z,qa.w,qbv.x,qbv.y,qbv.z,qbv.w};
            float rk[4] = {kf.x,kf.y,kf.z,kf.w};
            #pragma unroll
            for (int i = 0; i < 8; i++)
                #pragma unroll
                for (int j = 0; j < 4; j++)
                    s[i][j] += rq[i] * rk[j];
        }

        // Mask + online softmax (log2 domain)
        #pragma unroll
        for (int i = 0; i < 8; i++) {
            const int qrow = q0 + ty*8 + i;
            int4 mv = *(const int4*)(mb + (size_t)qrow * LL + k0 + tx*4);
            float v0 = mv.x ? s[i][0]*cs : 0.0f;
            float v1 = mv.y ? s[i][1]*cs : 0.0f;
            float v2 = mv.z ? s[i][2]*cs : 0.0f;
            float v3 = mv.w ? s[i][3]*cs : 0.0f;
            float tmax = fmaxf(fmaxf(v0, v1), fmaxf(v2, v3));
            #pragma unroll
            for (int mm = 1; mm < 16; mm <<= 1)
                tmax = fmaxf(tmax, __shfl_xor_sync(0xffffffffu, tmax, mm));
            float mnew = fmaxf(mi[i], tmax);
            float sc = fexp2(mi[i] - mnew);
            mi[i] = mnew;
            float p0 = fexp2(v0 - mnew);
            float p1 = fexp2(v1 - mnew);
            float p2 = fexp2(v2 - mnew);
            float p3 = fexp2(v3 - mnew);
            float rs = (p0 + p1) + (p2 + p3);   // masked entries count in denom
            #pragma unroll
            for (int mm = 1; mm < 16; mm <<= 1)
                rs += __shfl_xor_sync(0xffffffffu, rs, mm);
            li[i] = li[i] * sc + rs;
            o[i][0] *= sc; o[i][1] *= sc; o[i][2] *= sc; o[i][3] *= sc;
            // masked attention weights are zero for the PV product
            Ps[tx*4+0][ty*8+i] = mv.x ? p0 : 0.0f;
            Ps[tx*4+1][ty*8+i] = mv.y ? p1 : 0.0f;
            Ps[tx*4+2][ty*8+i] = mv.z ? p2 : 0.0f;
            Ps[tx*4+3][ty*8+i] = mv.w ? p3 : 0.0f;
        }
        __syncthreads();

        // O += P @ V ; thread: rows ty*8+i, dims tx*4+j
        #pragma unroll 8
        for (int k = 0; k < 64; k++) {
            float4 pa = *(const float4*)&Ps[k][ty*8];
            float4 pb = *(const float4*)&Ps[k][ty*8+4];
            float4 vf = *(const float4*)&Vs[k][tx*4];
            float rp[8] = {pa.x,pa.y,pa.z,pa.w,pb.x,pb.y,pb.z,pb.w};
            float rv[4] = {vf.x,vf.y,vf.z,vf.w};
            #pragma unroll
            for (int i = 0; i < 8; i++)
                #pragma unroll
                for (int j = 0; j < 4; j++)
                    o[i][j] += rp[i] * rv[j];
        }
    }

    // ctx[b, q, h*64 + dim] = O / l
    #pragma unroll
    for (int i = 0; i < 8; i++) {
        float inv = 1.0f / li[i];
        float4 w = {o[i][0]*inv, o[i][1]*inv, o[i][2]*inv, o[i][3]*inv};
        *(float4*)(ctx + (size_t)(rowbase + q0 + ty*8 + i) * DD + h * DKK + tx*4) = w;
    }
}

// ---------------------------------------------------------------------------
extern "C" void kernel_launch(void* const* d_in, const int* in_sizes, int n_in,
                              void* d_out, int out_size)
{
    const float* inputs = (const float*)d_in[0];
    const int*   mask   = (const int*)  d_in[1];
    const float* W1     = (const float*)d_in[2];
    const float* b1     = (const float*)d_in[3];
    const float* W2     = (const float*)d_in[4];
    const float* b2     = (const float*)d_in[5];
    float* out = (float*)d_out;

    float* qkv = nullptr;
    float* ctx = nullptr;
    cudaGetSymbolAddress((void**)&qkv, g_qkv);
    cudaGetSymbolAddress((void**)&ctx, g_ctx);

    // 1) QKV projection: [8192,1024] @ [1024,3072] + b1
    {
        dim3 grid(3*DD/128, NROWS/128);
        sgemm_bias<<<grid, 256>>>(inputs, W1, b1, qkv, NROWS, 3*DD, DD);
    }

    // 2) Fused masked attention -> ctx [8192,1024]
    {
        static_assert(ATTN_SMEM_FLOATS * sizeof(float) == 102400, "smem size");
        cudaFuncSetAttribute(attn_kernel,
                             cudaFuncAttributeMaxDynamicSharedMemorySize,
                             ATTN_SMEM_FLOATS * (int)sizeof(float));
        dim3 grid(LL/128, BB*HH);
        attn_kernel<<<grid, 256, ATTN_SMEM_FLOATS * sizeof(float)>>>(qkv, mask, ctx);
    }

    // 3) Output projection: [8192,1024] @ [1024,1024] + b2
    {
        dim3 grid(DD/128, NROWS/128);
        sgemm_bias<<<grid, 256>>>(ctx, W2, b2, out, NROWS, DD, DD);
    }
}

// round 3
// speedup vs baseline: 1.1962x; 1.1962x over previous
#include <cuda_runtime.h>
#include <cstdint>

#define BB 4
#define LL 2048
#define DD 1024
#define HH 16
#define DKK 64
#define NROWS (BB*LL)

// Scratch (allocation-free rule: __device__ globals)
__device__ float g_qkv[(size_t)NROWS * 3 * DD];   // [8192, 3072] : Q|K|V
__device__ float g_ctx[(size_t)NROWS * DD];       // [8192, 1024]

__device__ __forceinline__ float fexp2(float x) {
    float y; asm("ex2.approx.ftz.f32 %0, %1;" : "=f"(y) : "f"(x)); return y;
}

__device__ __forceinline__ void cp_async16(void* smem_dst, const void* gmem_src) {
    uint32_t s = (uint32_t)__cvta_generic_to_shared(smem_dst);
    asm volatile("cp.async.cg.shared.global [%0], [%1], 16;\n" :: "r"(s), "l"(gmem_src));
}
#define CP_COMMIT() asm volatile("cp.async.commit_group;\n" ::: "memory")
#define CP_WAIT1()  asm volatile("cp.async.wait_group 1;\n" ::: "memory")
#define CP_WAIT0()  asm volatile("cp.async.wait_group 0;\n" ::: "memory")

// Round-to-nearest fp32 -> tf32 (bit pattern is valid fp32 with low 13 bits 0)
__device__ __forceinline__ uint32_t f2tf(float x) {
    uint32_t r; asm("cvt.rna.tf32.f32 %0, %1;" : "=r"(r) : "f"(x)); return r;
}
// 3xTF32 split: x ~= hi + lo with ~fp32 total precision
__device__ __forceinline__ void tfsplit(float x, uint32_t& hi, uint32_t& lo) {
    hi = f2tf(x);
    lo = f2tf(x - __uint_as_float(hi));
}

// tf32 m16n8k8: D += A(16x8) * B(8x8), fp32 accumulate.
__device__ __forceinline__ void mma_tf32(float c[4], const uint32_t a[4], const uint32_t b[2]) {
    asm volatile(
        "mma.sync.aligned.m16n8k8.row.col.f32.tf32.tf32.f32 "
        "{%0,%1,%2,%3}, {%4,%5,%6,%7}, {%8,%9}, {%0,%1,%2,%3};\n"
        : "+f"(c[0]), "+f"(c[1]), "+f"(c[2]), "+f"(c[3])
        : "r"(a[0]), "r"(a[1]), "r"(a[2]), "r"(a[3]), "r"(b[0]), "r"(b[1]));
}
// 3-pass: c += (ah+al)*(bh+bl) minus lo*lo term
__device__ __forceinline__ void mma3(float c[4], const uint32_t ah[4], const uint32_t al[4],
                                     const uint32_t bh[2], const uint32_t bl[2]) {
    mma_tf32(c, ah, bh);
    mma_tf32(c, ah, bl);
    mma_tf32(c, al, bh);
}

// ---------------------------------------------------------------------------
// 3xTF32 tensor-core GEMM: C = A(M,K) @ W(K,N) + bias. M%128==0,N%128==0,K%32==0
// 128x128x32 tile, 256 threads (8 warps as 4x2), warp tile 32x64.
// Double-buffered smem via cp.async.
// ---------------------------------------------------------------------------
#define GEMM_SMEM_BYTES (2*128*36*4 + 2*32*136*4)   // 71680

__global__ __launch_bounds__(256, 1)
void mma_gemm(const float* __restrict__ A, const float* __restrict__ W,
              const float* __restrict__ bias, float* __restrict__ C,
              int M, int N, int K)
{
    extern __shared__ __align__(16) char smem_raw[];
    float (*As)[128][36] = (float(*)[128][36])(smem_raw);
    float (*Bs)[32][136] = (float(*)[32][136])(smem_raw + 2*128*36*4);

    const int tid  = threadIdx.x;
    const int warp = tid >> 5, lane = tid & 31;
    const int g = lane >> 2, t = lane & 3;
    const int wr = (warp >> 1) * 32;
    const int wc = (warp & 1) * 64;
    const int row0 = blockIdx.y * 128;
    const int col0 = blockIdx.x * 128;

    const int a_r = tid >> 3;
    const int a_c = (tid & 7) * 4;
    const int b_r = tid >> 5;
    const int b_c = (tid & 31) * 4;

    const int ntiles = K / 32;

    auto load_tile = [&](int kt, int buf) {
        const float* Ab = A + (size_t)(row0 + a_r) * K + kt * 32 + a_c;
        #pragma unroll
        for (int p = 0; p < 4; p++)
            cp_async16(&As[buf][a_r + 32*p][a_c], Ab + (size_t)32 * p * K);
        const float* Wb = W + (size_t)(kt * 32 + b_r) * N + col0 + b_c;
        #pragma unroll
        for (int p = 0; p < 4; p++)
            cp_async16(&Bs[buf][b_r + 8*p][b_c], Wb + (size_t)8 * p * N);
    };

    float acc[2][8][4];
    #pragma unroll
    for (int mi = 0; mi < 2; mi++)
        #pragma unroll
        for (int ni = 0; ni < 8; ni++)
            #pragma unroll
            for (int j = 0; j < 4; j++) acc[mi][ni][j] = 0.0f;

    load_tile(0, 0);
    CP_COMMIT();

    for (int kt = 0; kt < ntiles; kt++) {
        const int buf = kt & 1;
        if (kt + 1 < ntiles) {
            __syncthreads();
            load_tile(kt + 1, buf ^ 1);
            CP_COMMIT();
            CP_WAIT1();
        } else {
            CP_WAIT0();
        }
        __syncthreads();

        #pragma unroll
        for (int ks = 0; ks < 4; ks++) {
            uint32_t bh[8][2], bl[8][2];
            #pragma unroll
            for (int ni = 0; ni < 8; ni++) {
                tfsplit(Bs[buf][ks*8 + t    ][wc + ni*8 + g], bh[ni][0], bl[ni][0]);
                tfsplit(Bs[buf][ks*8 + t + 4][wc + ni*8 + g], bh[ni][1], bl[ni][1]);
            }
            uint32_t ah[2][4], al[2][4];
            #pragma unroll
            for (int mi = 0; mi < 2; mi++) {
                const int r = wr + mi*16 + g;
                tfsplit(As[buf][r    ][ks*8 + t    ], ah[mi][0], al[mi][0]);
                tfsplit(As[buf][r + 8][ks*8 + t    ], ah[mi][1], al[mi][1]);
                tfsplit(As[buf][r    ][ks*8 + t + 4], ah[mi][2], al[mi][2]);
                tfsplit(As[buf][r + 8][ks*8 + t + 4], ah[mi][3], al[mi][3]);
            }
            #pragma unroll
            for (int mi = 0; mi < 2; mi++)
                #pragma unroll
                for (int ni = 0; ni < 8; ni++)
                    mma3(acc[mi][ni], ah[mi], al[mi], bh[ni], bl[ni]);
        }
    }

    #pragma unroll
    for (int mi = 0; mi < 2; mi++) {
        const int r = row0 + wr + mi*16 + g;
        #pragma unroll
        for (int ni = 0; ni < 8; ni++) {
            const int c = col0 + wc + ni*8 + 2*t;
            float2 bb = *(const float2*)&bias[c];
            float2 v0 = {acc[mi][ni][0] + bb.x, acc[mi][ni][1] + bb.y};
            float2 v1 = {acc[mi][ni][2] + bb.x, acc[mi][ni][3] + bb.y};
            *(float2*)&C[(size_t)r * N + c]       = v0;
            *(float2*)&C[(size_t)(r + 8) * N + c] = v1;
        }
    }
}

// ---------------------------------------------------------------------------
// Fused masked flash attention, 3xTF32 mma.
// Block: 256 threads / 8 warps; warp w owns query rows [16w, 16w+16).
// BM=128 queries, BN=64 keys per iter, DK=64. Q hi/lo frags in registers.
// Masked score -> 0.0 (counts in max + denominator), attn weight zeroed for PV.
// ---------------------------------------------------------------------------
#define ATTN_SMEM_BYTES (128*68*4 + 2*64*68*4 + 2*64*72*4)  // 106496

__global__ __launch_bounds__(256, 1)
void attn_mma(const float* __restrict__ qkv, const int* __restrict__ mask,
              float* __restrict__ ctx)
{
    extern __shared__ __align__(16) char smem_raw[];
    float (*PQ)[68]     = (float(*)[68])(smem_raw);                 // Q stage, then P
    float (*Ks)[64][68] = (float(*)[64][68])(smem_raw + 128*68*4);
    float (*Vs)[64][72] = (float(*)[64][72])(smem_raw + 128*68*4 + 2*64*68*4);

    const int tid  = threadIdx.x;
    const int warp = tid >> 5, lane = tid & 31;
    const int g = lane >> 2, t = lane & 3;
    const int b  = blockIdx.y >> 4;
    const int h  = blockIdx.y & 15;
    const int q0 = blockIdx.x * 128;

    const size_t rowbase = (size_t)b * LL;
    const float* qb = qkv + rowbase * (3*DD) + h * DKK;
    const float* kb = qb + DD;
    const float* vb = qb + 2*DD;
    const int*   mb = mask + (size_t)b * LL * LL;

    const int kv_r = tid >> 2;
    const int kv_c = (tid & 3) * 16;

    auto load_kv = [&](int tile, int buf) {
        const int k0 = tile * 64;
        const float* Kb = kb + (size_t)(k0 + kv_r) * (3*DD) + kv_c;
        const float* Vb = vb + (size_t)(k0 + kv_r) * (3*DD) + kv_c;
        #pragma unroll
        for (int p = 0; p < 4; p++) {
            cp_async16(&Ks[buf][kv_r][kv_c + 4*p], Kb + 4*p);
            cp_async16(&Vs[buf][kv_r][kv_c + 4*p], Vb + 4*p);
        }
    };

    load_kv(0, 0);
    CP_COMMIT();

    // Q staging -> register fragments (hi/lo)
    {
        #pragma unroll
        for (int p = 0; p < 8; p++) {
            int idx  = p * 32 + lane;
            int r16  = idx >> 4;
            int ch   = (idx & 15) * 4;
            float4 v = *(const float4*)(qb + (size_t)(q0 + warp*16 + r16) * (3*DD) + ch);
            *(float4*)&PQ[warp*16 + r16][ch] = v;
        }
    }
    __syncwarp();
    uint32_t aqh[8][4], aql[8][4];
    {
        const int r = warp*16 + g;
        #pragma unroll
        for (int ks = 0; ks < 8; ks++) {
            tfsplit(PQ[r    ][ks*8 + t    ], aqh[ks][0], aql[ks][0]);
            tfsplit(PQ[r + 8][ks*8 + t    ], aqh[ks][1], aql[ks][1]);
            tfsplit(PQ[r    ][ks*8 + t + 4], aqh[ks][2], aql[ks][2]);
            tfsplit(PQ[r + 8][ks*8 + t + 4], aqh[ks][3], aql[ks][3]);
        }
    }
    __syncwarp();   // warp's PQ slice now reusable as P

    float oc[8][4];
    #pragma unroll
    for (int ni = 0; ni < 8; ni++)
        #pragma unroll
        for (int j = 0; j < 4; j++) oc[ni][j] = 0.0f;
    float mi0 = -1e30f, mi1 = -1e30f, li0 = 0.0f, li1 = 0.0f;

    const float cs = 0.18033688011112042f;  // log2(e) / sqrt(64)
    const int lr0 = warp*16 + g;
    const int r0g = q0 + lr0;
    const int NT  = LL / 64;

    for (int tt = 0; tt < NT; tt++) {
        const int buf = tt & 1;
        const int k0  = tt * 64;
        if (tt + 1 < NT) {
            __syncthreads();
            load_kv(tt + 1, buf ^ 1);
            CP_COMMIT();
            CP_WAIT1();
        } else {
            CP_WAIT0();
        }
        __syncthreads();

        // S = Q @ K^T : warp tile 16x64, 3xTF32
        float sc[8][4];
        #pragma unroll
        for (int ni = 0; ni < 8; ni++)
            #pragma unroll
            for (int j = 0; j < 4; j++) sc[ni][j] = 0.0f;

        #pragma unroll
        for (int ks = 0; ks < 8; ks++) {
            #pragma unroll
            for (int ni = 0; ni < 8; ni++) {
                uint32_t kh[2], kl[2];
                tfsplit(Ks[buf][ni*8 + g][ks*8 + t    ], kh[0], kl[0]);
                tfsplit(Ks[buf][ni*8 + g][ks*8 + t + 4], kh[1], kl[1]);
                mma3(sc[ni], aqh[ks], aql[ks], kh, kl);
            }
        }

        // Mask + online softmax (log2 domain). Masked -> 0.0 in max+denom, p=0.
        uint32_t bits0 = 0, bits1 = 0;
        float tm0 = -1e30f, tm1 = -1e30f;
        #pragma unroll
        for (int ni = 0; ni < 8; ni++) {
            const int c = k0 + ni*8 + 2*t;
            int2 m0 = *(const int2*)(mb + (size_t)r0g * LL + c);
            int2 m1 = *(const int2*)(mb + (size_t)(r0g + 8) * LL + c);
            sc[ni][0] = m0.x ? sc[ni][0]*cs : 0.0f;
            sc[ni][1] = m0.y ? sc[ni][1]*cs : 0.0f;
            sc[ni][2] = m1.x ? sc[ni][2]*cs : 0.0f;
            sc[ni][3] = m1.y ? sc[ni][3]*cs : 0.0f;
            bits0 |= (m0.x ? 1u : 0u) << (ni*2);
            bits0 |= (m0.y ? 1u : 0u) << (ni*2 + 1);
            bits1 |= (m1.x ? 1u : 0u) << (ni*2);
            bits1 |= (m1.y ? 1u : 0u) << (ni*2 + 1);
            tm0 = fmaxf(tm0, fmaxf(sc[ni][0], sc[ni][1]));
            tm1 = fmaxf(tm1, fmaxf(sc[ni][2], sc[ni][3]));
        }
        tm0 = fmaxf(tm0, __shfl_xor_sync(0xffffffffu, tm0, 1));
        tm0 = fmaxf(tm0, __shfl_xor_sync(0xffffffffu, tm0, 2));
        tm1 = fmaxf(tm1, __shfl_xor_sync(0xffffffffu, tm1, 1));
        tm1 = fmaxf(tm1, __shfl_xor_sync(0xffffffffu, tm1, 2));

        const float mn0 = fmaxf(mi0, tm0);
        const float mn1 = fmaxf(mi1, tm1);
        const float s0  = fexp2(mi0 - mn0);
        const float s1  = fexp2(mi1 - mn1);
        mi0 = mn0; mi1 = mn1;

        float sum0 = 0.0f, sum1 = 0.0f;
        #pragma unroll
        for (int ni = 0; ni < 8; ni++) {
            float e0 = fexp2(sc[ni][0] - mn0);
            float e1 = fexp2(sc[ni][1] - mn0);
            float e2 = fexp2(sc[ni][2] - mn1);
            float e3 = fexp2(sc[ni][3] - mn1);
            sum0 += e0 + e1;
            sum1 += e2 + e3;
            float2 p0 = {(bits0 >> (ni*2)) & 1 ? e0 : 0.0f,
                         (bits0 >> (ni*2+1)) & 1 ? e1 : 0.0f};
            float2 p1 = {(bits1 >> (ni*2)) & 1 ? e2 : 0.0f,
                         (bits1 >> (ni*2+1)) & 1 ? e3 : 0.0f};
            *(float2*)&PQ[lr0    ][ni*8 + 2*t] = p0;
            *(float2*)&PQ[lr0 + 8][ni*8 + 2*t] = p1;
        }
        sum0 += __shfl_xor_sync(0xffffffffu, sum0, 1);
        sum0 += __shfl_xor_sync(0xffffffffu, sum0, 2);
        sum1 += __shfl_xor_sync(0xffffffffu, sum1, 1);
        sum1 += __shfl_xor_sync(0xffffffffu, sum1, 2);
        li0 = li0 * s0 + sum0;
        li1 = li1 * s1 + sum1;

        #pragma unroll
        for (int ni = 0; ni < 8; ni++) {
            oc[ni][0] *= s0; oc[ni][1] *= s0;
            oc[ni][2] *= s1; oc[ni][3] *= s1;
        }
        __syncwarp();   // P visible within warp

        // O += P @ V : 3xTF32
        #pragma unroll
        for (int ks = 0; ks < 8; ks++) {
            uint32_t aph[4], apl[4];
            tfsplit(PQ[lr0    ][ks*8 + t    ], aph[0], apl[0]);
            tfsplit(PQ[lr0 + 8][ks*8 + t    ], aph[1], apl[1]);
            tfsplit(PQ[lr0    ][ks*8 + t + 4], aph[2], apl[2]);
            tfsplit(PQ[lr0 + 8][ks*8 + t + 4], aph[3], apl[3]);
            #pragma unroll
            for (int ni = 0; ni < 8; ni++) {
                uint32_t vh[2], vl[2];
                tfsplit(Vs[buf][ks*8 + t    ][ni*8 + g], vh[0], vl[0]);
                tfsplit(Vs[buf][ks*8 + t + 4][ni*8 + g], vh[1], vl[1]);
                mma3(oc[ni], aph, apl, vh, vl);
            }
        }
        __syncwarp();   // done reading P before next iter overwrites
    }

    // ctx[b, q, h*64 + d] = O / l
    const float inv0 = 1.0f / li0;
    const float inv1 = 1.0f / li1;
    #pragma unroll
    for (int ni = 0; ni < 8; ni++) {
        const int c = h*DKK + ni*8 + 2*t;
        float2 w0 = {oc[ni][0]*inv0, oc[ni][1]*inv0};
        float2 w1 = {oc[ni][2]*inv1, oc[ni][3]*inv1};
        *(float2*)(ctx + (size_t)(rowbase + r0g)     * DD + c) = w0;
        *(float2*)(ctx + (size_t)(rowbase + r0g + 8) * DD + c) = w1;
    }
}

// ---------------------------------------------------------------------------
extern "C" void kernel_launch(void* const* d_in, const int* in_sizes, int n_in,
                              void* d_out, int out_size)
{
    const float* inputs = (const float*)d_in[0];
    const int*   mask   = (const int*)  d_in[1];
    const float* W1     = (const float*)d_in[2];
    const float* b1     = (const float*)d_in[3];
    const float* W2     = (const float*)d_in[4];
    const float* b2     = (const float*)d_in[5];
    float* out = (float*)d_out;

    float* qkv = nullptr;
    float* ctx = nullptr;
    cudaGetSymbolAddress((void**)&qkv, g_qkv);
    cudaGetSymbolAddress((void**)&ctx, g_ctx);

    cudaFuncSetAttribute(mma_gemm, cudaFuncAttributeMaxDynamicSharedMemorySize,
                         GEMM_SMEM_BYTES);
    cudaFuncSetAttribute(attn_mma, cudaFuncAttributeMaxDynamicSharedMemorySize,
                         ATTN_SMEM_BYTES);

    {   // 1) QKV projection
        dim3 grid(3*DD/128, NROWS/128);
        mma_gemm<<<grid, 256, GEMM_SMEM_BYTES>>>(inputs, W1, b1, qkv, NROWS, 3*DD, DD);
    }
    {   // 2) Fused masked attention
        dim3 grid(LL/128, BB*HH);
        attn_mma<<<grid, 256, ATTN_SMEM_BYTES>>>(qkv, mask, ctx);
    }
    {   // 3) Output projection
        dim3 grid(DD/128, NROWS/128);
        mma_gemm<<<grid, 256, GEMM_SMEM_BYTES>>>(ctx, W2, b2, out, NROWS, DD, DD);
    }
}

// round 4
// speedup vs baseline: 2.2351x; 1.8685x over previous
#include <cuda_runtime.h>
#include <cuda_bf16.h>
#include <cstdint>

#define BB 4
#define LL 2048
#define DD 1024
#define HH 16
#define NROWS (BB*LL)
#define D3 (3*DD)

// ---------------- persistent bf16 hi/lo planes (allocation-free scratch) ----
__device__ __nv_bfloat16 g_xh[(size_t)NROWS*DD],  g_xl[(size_t)NROWS*DD];
__device__ __nv_bfloat16 g_w1h[(size_t)DD*D3],    g_w1l[(size_t)DD*D3];
__device__ __nv_bfloat16 g_w2h[(size_t)DD*DD],    g_w2l[(size_t)DD*DD];
__device__ __nv_bfloat16 g_qh[(size_t)NROWS*D3],  g_ql[(size_t)NROWS*D3];
__device__ __nv_bfloat16 g_ch[(size_t)NROWS*DD],  g_cl[(size_t)NROWS*DD];

// ---------------- helpers ---------------------------------------------------
__device__ __forceinline__ float fexp2(float x) {
    float y; asm("ex2.approx.ftz.f32 %0, %1;" : "=f"(y) : "f"(x)); return y;
}
__device__ __forceinline__ void cp_async16(void* smem_dst, const void* gmem_src) {
    uint32_t s = (uint32_t)__cvta_generic_to_shared(smem_dst);
    asm volatile("cp.async.cg.shared.global [%0], [%1], 16;\n" :: "r"(s), "l"(gmem_src));
}
#define CP_COMMIT() asm volatile("cp.async.commit_group;\n" ::: "memory")
#define CP_WAIT1()  asm volatile("cp.async.wait_group 1;\n" ::: "memory")
#define CP_WAIT0()  asm volatile("cp.async.wait_group 0;\n" ::: "memory")

__device__ __forceinline__ uint32_t su32(const void* p) {
    return (uint32_t)__cvta_generic_to_shared(p);
}
// pack two floats -> bf16x2 (x -> low half = first k element)
__device__ __forceinline__ uint32_t packbf(float x, float y) {
    uint32_t r;
    asm("cvt.rn.satfinite.bf16x2.f32 %0, %1, %2;" : "=r"(r) : "f"(y), "f"(x));
    return r;
}
// split (x,y) into hi-pack and lo-pack (lo = exact fp32 residual rounded to bf16)
__device__ __forceinline__ void split_pair(float x, float y, uint32_t& hp, uint32_t& lp) {
    hp = packbf(x, y);
    float hx = __uint_as_float(hp << 16);
    float hy = __uint_as_float(hp & 0xffff0000u);
    lp = packbf(x - hx, y - hy);
}
// bf16 m16n8k16: C += A*B, fp32 accumulate
__device__ __forceinline__ void mma_bf16(float c[4], const uint32_t a[4],
                                         uint32_t b0, uint32_t b1) {
    asm volatile(
        "mma.sync.aligned.m16n8k16.row.col.f32.bf16.bf16.f32 "
        "{%0,%1,%2,%3}, {%4,%5,%6,%7}, {%8,%9}, {%0,%1,%2,%3};\n"
        : "+f"(c[0]), "+f"(c[1]), "+f"(c[2]), "+f"(c[3])
        : "r"(a[0]), "r"(a[1]), "r"(a[2]), "r"(a[3]), "r"(b0), "r"(b1));
}
__device__ __forceinline__ void ldsm_x4(uint32_t r[4], uint32_t addr) {
    asm volatile("ldmatrix.sync.aligned.m8n8.x4.shared.b16 {%0,%1,%2,%3}, [%4];"
        : "=r"(r[0]), "=r"(r[1]), "=r"(r[2]), "=r"(r[3]) : "r"(addr));
}
__device__ __forceinline__ void ldsm_x4_t(uint32_t r[4], uint32_t addr) {
    asm volatile("ldmatrix.sync.aligned.m8n8.x4.trans.shared.b16 {%0,%1,%2,%3}, [%4];"
        : "=r"(r[0]), "=r"(r[1]), "=r"(r[2]), "=r"(r[3]) : "r"(addr));
}

// ---------------- pre-pass: fp32 -> bf16 hi/lo planes -----------------------
__global__ void split_kernel(const float* __restrict__ src,
                             __nv_bfloat16* __restrict__ h,
                             __nv_bfloat16* __restrict__ l, int n4) {
    int i = blockIdx.x * 256 + threadIdx.x;
    if (i >= n4) return;
    float4 v = ((const float4*)src)[i];
    uint32_t h0, l0, h1, l1;
    split_pair(v.x, v.y, h0, l0);
    split_pair(v.z, v.w, h1, l1);
    ((uint2*)h)[i] = make_uint2(h0, h1);
    ((uint2*)l)[i] = make_uint2(l0, l1);
}

// ---------------------------------------------------------------------------
// bf16x3 GEMM: C = A(M,K) @ W(K,N) + bias.  A,W pre-split hi/lo bf16 planes.
// 128x128x32 tile, 256 threads (8 warps 4x2), warp tile 32x64, cp.async 2-buf.
// Smem pads: As rows 40 bf16 (20-word stride), Bs rows 136 bf16 (68-word).
// SPLIT_OUT: write hi/lo bf16 planes (intermediate) else fp32.
// ---------------------------------------------------------------------------
#define AS_PAD 40
#define BS_PAD 136
#define GEMM_SMEM_BYTES (2*128*AS_PAD*2*2 + 2*32*BS_PAD*2*2)   // 40960+34816=75776

template<bool SPLIT_OUT>
__global__ __launch_bounds__(256, 1)
void gemm_bf16x3(const __nv_bfloat16* __restrict__ Ah, const __nv_bfloat16* __restrict__ Al,
                 const __nv_bfloat16* __restrict__ Wh, const __nv_bfloat16* __restrict__ Wl,
                 const float* __restrict__ bias, float* __restrict__ Cf,
                 __nv_bfloat16* __restrict__ Ch, __nv_bfloat16* __restrict__ Cl,
                 int M, int N, int K)
{
    extern __shared__ __align__(16) char smem_raw[];
    __nv_bfloat16 (*AsH)[128][AS_PAD] = (__nv_bfloat16(*)[128][AS_PAD])(smem_raw);
    __nv_bfloat16 (*AsL)[128][AS_PAD] = (__nv_bfloat16(*)[128][AS_PAD])(smem_raw + 20480);
    __nv_bfloat16 (*BsH)[32][BS_PAD]  = (__nv_bfloat16(*)[32][BS_PAD]) (smem_raw + 40960);
    __nv_bfloat16 (*BsL)[32][BS_PAD]  = (__nv_bfloat16(*)[32][BS_PAD]) (smem_raw + 58368);

    const int tid  = threadIdx.x;
    const int warp = tid >> 5, lane = tid & 31;
    const int g = lane >> 2, t = lane & 3;
    const int wr = (warp >> 1) * 32;
    const int wc = (warp & 1) * 64;
    const int row0 = blockIdx.y * 128;
    const int col0 = blockIdx.x * 128;
    const int ntiles = K / 32;

    const int a_m = tid >> 1;              // 0..127
    const int a_c = (tid & 1) * 2;         // chunk pair base (of 4 chunks)
    const int b_k = tid >> 3;              // 0..31
    const int b_c = tid & 7;               // chunk (of 16)

    auto load_tile = [&](int kt, int buf) {
        const __nv_bfloat16* ah = Ah + (size_t)(row0 + a_m) * K + kt*32;
        const __nv_bfloat16* al = Al + (size_t)(row0 + a_m) * K + kt*32;
        #pragma unroll
        for (int c = 0; c < 2; c++) {
            cp_async16(&AsH[buf][a_m][(a_c + c) * 8], ah + (a_c + c) * 8);
            cp_async16(&AsL[buf][a_m][(a_c + c) * 8], al + (a_c + c) * 8);
        }
        const __nv_bfloat16* wh = Wh + (size_t)(kt*32 + b_k) * N + col0;
        const __nv_bfloat16* wl = Wl + (size_t)(kt*32 + b_k) * N + col0;
        #pragma unroll
        for (int c = 0; c < 2; c++) {
            cp_async16(&BsH[buf][b_k][(b_c + 8*c) * 8], wh + (b_c + 8*c) * 8);
            cp_async16(&BsL[buf][b_k][(b_c + 8*c) * 8], wl + (b_c + 8*c) * 8);
        }
    };

    float acc[2][8][4];
    #pragma unroll
    for (int mi = 0; mi < 2; mi++)
        #pragma unroll
        for (int ni = 0; ni < 8; ni++)
            #pragma unroll
            for (int j = 0; j < 4; j++) acc[mi][ni][j] = 0.0f;

    load_tile(0, 0);
    CP_COMMIT();

    // ldmatrix lane geometry
    const int a_row = (lane & 15);                 // + wr + mi*16
    const int a_col = (lane >> 4) << 3;            // + k0
    const int b_row = (lane & 15);                 // + k0
    const int b_col = (lane >> 4) << 3;            // + n0

    for (int kt = 0; kt < ntiles; kt++) {
        const int buf = kt & 1;
        if (kt + 1 < ntiles) {
            __syncthreads();
            load_tile(kt + 1, buf ^ 1);
            CP_COMMIT();
            CP_WAIT1();
        } else {
            CP_WAIT0();
        }
        __syncthreads();

        #pragma unroll
        for (int ks = 0; ks < 2; ks++) {
            const int k0 = ks * 16;
            uint32_t aH[2][4], aL[2][4];
            #pragma unroll
            for (int mi = 0; mi < 2; mi++) {
                ldsm_x4(aH[mi], su32(&AsH[buf][wr + mi*16 + a_row][k0 + a_col]));
                ldsm_x4(aL[mi], su32(&AsL[buf][wr + mi*16 + a_row][k0 + a_col]));
            }
            #pragma unroll
            for (int njp = 0; njp < 4; njp++) {
                const int n0 = wc + njp * 16;
                uint32_t bH[4], bL[4];
                ldsm_x4_t(bH, su32(&BsH[buf][k0 + b_row][n0 + b_col]));
                ldsm_x4_t(bL, su32(&BsL[buf][k0 + b_row][n0 + b_col]));
                #pragma unroll
                for (int mi = 0; mi < 2; mi++) {
                    mma_bf16(acc[mi][2*njp],   aH[mi], bH[0], bH[1]);
                    mma_bf16(acc[mi][2*njp],   aH[mi], bL[0], bL[1]);
                    mma_bf16(acc[mi][2*njp],   aL[mi], bH[0], bH[1]);
                    mma_bf16(acc[mi][2*njp+1], aH[mi], bH[2], bH[3]);
                    mma_bf16(acc[mi][2*njp+1], aH[mi], bL[2], bL[3]);
                    mma_bf16(acc[mi][2*njp+1], aL[mi], bH[2], bH[3]);
                }
            }
        }
    }

    #pragma unroll
    for (int mi = 0; mi < 2; mi++) {
        const int r = row0 + wr + mi*16 + g;
        #pragma unroll
        for (int ni = 0; ni < 8; ni++) {
            const int c = col0 + wc + ni*8 + 2*t;
            float2 bb = *(const float2*)&bias[c];
            float v0 = acc[mi][ni][0] + bb.x, v1 = acc[mi][ni][1] + bb.y;
            float v2 = acc[mi][ni][2] + bb.x, v3 = acc[mi][ni][3] + bb.y;
            if (SPLIT_OUT) {
                uint32_t hp, lp;
                split_pair(v0, v1, hp, lp);
                *(uint32_t*)&Ch[(size_t)r * N + c] = hp;
                *(uint32_t*)&Cl[(size_t)r * N + c] = lp;
                split_pair(v2, v3, hp, lp);
                *(uint32_t*)&Ch[(size_t)(r + 8) * N + c] = hp;
                *(uint32_t*)&Cl[(size_t)(r + 8) * N + c] = lp;
            } else {
                *(float2*)&Cf[(size_t)r * N + c]       = make_float2(v0, v1);
                *(float2*)&Cf[(size_t)(r + 8) * N + c] = make_float2(v2, v3);
            }
        }
    }
}

// ---------------------------------------------------------------------------
// Fused masked flash attention, bf16x3. 256 thr / 8 warps; warp w owns query
// rows [16w,16w+16). BM=128, BN=64, DK=64. Q frags in regs; P repacked from S
// C-fragments in registers (no smem round-trip). K: ldmatrix normal on
// [key][dim]; V: ldmatrix.trans on [key][dim]. Masked score -> 0.0 (in max +
// denominator), attn weight zeroed for PV.
// ---------------------------------------------------------------------------
#define KV_PAD 72
#define ATTN_SMEM_BYTES (4 * 2*64*KV_PAD*2)   // KsH,KsL,VsH,VsL = 73728

__global__ __launch_bounds__(256, 1)
void attn_bf16x3(const __nv_bfloat16* __restrict__ qh, const __nv_bfloat16* __restrict__ ql,
                 const int* __restrict__ mask,
                 __nv_bfloat16* __restrict__ cth, __nv_bfloat16* __restrict__ ctl)
{
    extern __shared__ __align__(16) char smem_raw[];
    __nv_bfloat16 (*KsH)[64][KV_PAD] = (__nv_bfloat16(*)[64][KV_PAD])(smem_raw);
    __nv_bfloat16 (*KsL)[64][KV_PAD] = (__nv_bfloat16(*)[64][KV_PAD])(smem_raw + 18432);
    __nv_bfloat16 (*VsH)[64][KV_PAD] = (__nv_bfloat16(*)[64][KV_PAD])(smem_raw + 36864);
    __nv_bfloat16 (*VsL)[64][KV_PAD] = (__nv_bfloat16(*)[64][KV_PAD])(smem_raw + 55296);
    // Q staging reuses KsH(+KsL) area as [128][KV_PAD]
    __nv_bfloat16 (*QstH)[KV_PAD] = (__nv_bfloat16(*)[KV_PAD])(smem_raw);
    __nv_bfloat16 (*QstL)[KV_PAD] = (__nv_bfloat16(*)[KV_PAD])(smem_raw + 18432);

    const int tid  = threadIdx.x;
    const int warp = tid >> 5, lane = tid & 31;
    const int g = lane >> 2, t = lane & 3;
    const int b  = blockIdx.y >> 4;
    const int h  = blockIdx.y & 15;
    const int q0 = blockIdx.x * 128;

    const size_t rowbase = (size_t)b * LL;
    const int*   mb = mask + (size_t)b * LL * LL;

    // ---- stage Q planes, extract A-fragments --------------------------------
    {
        #pragma unroll
        for (int p = 0; p < 4; p++) {
            int idx = p * 256 + tid;
            int r   = idx >> 3;
            int ch  = (idx & 7) * 8;
            size_t src = (rowbase + q0 + r) * (size_t)D3 + h*64 + ch;
            cp_async16(&QstH[r][ch], qh + src);
            cp_async16(&QstL[r][ch], ql + src);
        }
    }
    CP_COMMIT();
    CP_WAIT0();
    __syncthreads();

    uint32_t aqH[4][4], aqL[4][4];
    {
        const int r = warp*16 + (lane & 15);
        const int cofs = (lane >> 4) << 3;
        #pragma unroll
        for (int kb = 0; kb < 4; kb++) {
            ldsm_x4(aqH[kb], su32(&QstH[r][kb*16 + cofs]));
            ldsm_x4(aqL[kb], su32(&QstL[r][kb*16 + cofs]));
        }
    }
    __syncthreads();   // staging area free -> becomes K buffers

    // ---- KV pipeline --------------------------------------------------------
    const int kv_r = tid >> 2;
    const int kv_c = (tid & 3) * 2;

    auto load_kv = [&](int tile, int buf) {
        const int k0 = tile * 64;
        size_t base = (rowbase + k0 + kv_r) * (size_t)D3 + h*64;
        #pragma unroll
        for (int c = 0; c < 2; c++) {
            int ch = (kv_c + c) * 8;
            cp_async16(&KsH[buf][kv_r][ch], qh + base + 1024 + ch);
            cp_async16(&KsL[buf][kv_r][ch], ql + base + 1024 + ch);
            cp_async16(&VsH[buf][kv_r][ch], qh + base + 2048 + ch);
            cp_async16(&VsL[buf][kv_r][ch], ql + base + 2048 + ch);
        }
    };

    load_kv(0, 0);
    CP_COMMIT();

    float oc[8][4];
    #pragma unroll
    for (int ni = 0; ni < 8; ni++)
        #pragma unroll
        for (int j = 0; j < 4; j++) oc[ni][j] = 0.0f;
    float mi0 = -1e30f, mi1 = -1e30f, li0 = 0.0f, li1 = 0.0f;

    const float cs = 0.18033688011112042f;  // log2(e)/sqrt(64)
    const int r0g = q0 + warp*16 + g;
    const int NT  = LL / 64;

    // ldmatrix lane geometry
    const int k_key = ((lane & 16) ? 8 : 0) + (lane & 7);   // + njp*16
    const int k_dim = (lane & 8) ? 8 : 0;                   // + kb*16
    const int v_row = lane;                                 // + kb2*32

    for (int tt = 0; tt < NT; tt++) {
        const int buf = tt & 1;
        const int k0  = tt * 64;
        if (tt + 1 < NT) {
            __syncthreads();
            load_kv(tt + 1, buf ^ 1);
            CP_COMMIT();
            CP_WAIT1();
        } else {
            CP_WAIT0();
        }
        __syncthreads();

        // ---- S = Q @ K^T (warp tile 16x64), bf16x3 --------------------------
        float sc[8][4];
        #pragma unroll
        for (int ni = 0; ni < 8; ni++)
            #pragma unroll
            for (int j = 0; j < 4; j++) sc[ni][j] = 0.0f;

        #pragma unroll
        for (int kb = 0; kb < 4; kb++) {
            #pragma unroll
            for (int njp = 0; njp < 4; njp++) {
                uint32_t kH[4], kL[4];
                ldsm_x4(kH, su32(&KsH[buf][njp*16 + k_key][kb*16 + k_dim]));
                ldsm_x4(kL, su32(&KsL[buf][njp*16 + k_key][kb*16 + k_dim]));
                mma_bf16(sc[2*njp],   aqH[kb], kH[0], kH[1]);
                mma_bf16(sc[2*njp],   aqH[kb], kL[0], kL[1]);
                mma_bf16(sc[2*njp],   aqL[kb], kH[0], kH[1]);
                mma_bf16(sc[2*njp+1], aqH[kb], kH[2], kH[3]);
                mma_bf16(sc[2*njp+1], aqH[kb], kL[2], kL[3]);
                mma_bf16(sc[2*njp+1], aqL[kb], kH[2], kH[3]);
            }
        }

        // ---- mask + online softmax (log2 domain) ----------------------------
        uint32_t bits0 = 0, bits1 = 0;
        float tm0 = -1e30f, tm1 = -1e30f;
        #pragma unroll
        for (int ni = 0; ni < 8; ni++) {
            const int c = k0 + ni*8 + 2*t;
            int2 m0 = *(const int2*)(mb + (size_t)r0g * LL + c);
            int2 m1 = *(const int2*)(mb + (size_t)(r0g + 8) * LL + c);
            sc[ni][0] = m0.x ? sc[ni][0]*cs : 0.0f;
            sc[ni][1] = m0.y ? sc[ni][1]*cs : 0.0f;
            sc[ni][2] = m1.x ? sc[ni][2]*cs : 0.0f;
            sc[ni][3] = m1.y ? sc[ni][3]*cs : 0.0f;
            bits0 |= (m0.x ? 1u : 0u) << (ni*2);
            bits0 |= (m0.y ? 1u : 0u) << (ni*2 + 1);
            bits1 |= (m1.x ? 1u : 0u) << (ni*2);
            bits1 |= (m1.y ? 1u : 0u) << (ni*2 + 1);
            tm0 = fmaxf(tm0, fmaxf(sc[ni][0], sc[ni][1]));
            tm1 = fmaxf(tm1, fmaxf(sc[ni][2], sc[ni][3]));
        }
        tm0 = fmaxf(tm0, __shfl_xor_sync(0xffffffffu, tm0, 1));
        tm0 = fmaxf(tm0, __shfl_xor_sync(0xffffffffu, tm0, 2));
        tm1 = fmaxf(tm1, __shfl_xor_sync(0xffffffffu, tm1, 1));
        tm1 = fmaxf(tm1, __shfl_xor_sync(0xffffffffu, tm1, 2));

        const float mn0 = fmaxf(mi0, tm0);
        const float mn1 = fmaxf(mi1, tm1);
        const float s0  = fexp2(mi0 - mn0);
        const float s1  = fexp2(mi1 - mn1);
        mi0 = mn0; mi1 = mn1;

        float sum0 = 0.0f, sum1 = 0.0f;
        #pragma unroll
        for (int ni = 0; ni < 8; ni++) {
            float e0 = fexp2(sc[ni][0] - mn0);
            float e1 = fexp2(sc[ni][1] - mn0);
            float e2 = fexp2(sc[ni][2] - mn1);
            float e3 = fexp2(sc[ni][3] - mn1);
            sum0 += e0 + e1;
            sum1 += e2 + e3;
            sc[ni][0] = ((bits0 >> (ni*2)) & 1)   ? e0 : 0.0f;
            sc[ni][1] = ((bits0 >> (ni*2+1)) & 1) ? e1 : 0.0f;
            sc[ni][2] = ((bits1 >> (ni*2)) & 1)   ? e2 : 0.0f;
            sc[ni][3] = ((bits1 >> (ni*2+1)) & 1) ? e3 : 0.0f;
        }
        sum0 += __shfl_xor_sync(0xffffffffu, sum0, 1);
        sum0 += __shfl_xor_sync(0xffffffffu, sum0, 2);
        sum1 += __shfl_xor_sync(0xffffffffu, sum1, 1);
        sum1 += __shfl_xor_sync(0xffffffffu, sum1, 2);
        li0 = li0 * s0 + sum0;
        li1 = li1 * s1 + sum1;

        #pragma unroll
        for (int ni = 0; ni < 8; ni++) {
            oc[ni][0] *= s0; oc[ni][1] *= s0;
            oc[ni][2] *= s1; oc[ni][3] *= s1;
        }

        // ---- O += P @ V : P repacked from sc in registers, bf16x3 -----------
        #pragma unroll
        for (int kb2 = 0; kb2 < 2; kb2++) {
            uint32_t apH[2][4], apL[2][4];
            #pragma unroll
            for (int kk = 0; kk < 2; kk++) {
                const int kbi = kb2*2 + kk;
                split_pair(sc[2*kbi][0],   sc[2*kbi][1],   apH[kk][0], apL[kk][0]);
                split_pair(sc[2*kbi][2],   sc[2*kbi][3],   apH[kk][1], apL[kk][1]);
                split_pair(sc[2*kbi+1][0], sc[2*kbi+1][1], apH[kk][2], apL[kk][2]);
                split_pair(sc[2*kbi+1][2], sc[2*kbi+1][3], apH[kk][3], apL[kk][3]);
            }
            #pragma unroll
            for (int nj = 0; nj < 8; nj++) {
                uint32_t vH[4], vL[4];
                ldsm_x4_t(vH, su32(&VsH[buf][kb2*32 + v_row][nj*8]));
                ldsm_x4_t(vL, su32(&VsL[buf][kb2*32 + v_row][nj*8]));
                mma_bf16(oc[nj], apH[0], vH[0], vH[1]);
                mma_bf16(oc[nj], apH[0], vL[0], vL[1]);
                mma_bf16(oc[nj], apL[0], vH[0], vH[1]);
                mma_bf16(oc[nj], apH[1], vH[2], vH[3]);
                mma_bf16(oc[nj], apH[1], vL[2], vL[3]);
                mma_bf16(oc[nj], apL[1], vH[2], vH[3]);
            }
        }
    }

    // ---- epilogue: ctx hi/lo planes ----------------------------------------
    const float inv0 = 1.0f / li0;
    const float inv1 = 1.0f / li1;
    #pragma unroll
    for (int ni = 0; ni < 8; ni++) {
        const int c = h*64 + ni*8 + 2*t;
        uint32_t hp, lp;
        split_pair(oc[ni][0]*inv0, oc[ni][1]*inv0, hp, lp);
        *(uint32_t*)&cth[(rowbase + r0g) * DD + c] = hp;
        *(uint32_t*)&ctl[(rowbase + r0g) * DD + c] = lp;
        split_pair(oc[ni][2]*inv1, oc[ni][3]*inv1, hp, lp);
        *(uint32_t*)&cth[(rowbase + r0g + 8) * DD + c] = hp;
        *(uint32_t*)&ctl[(rowbase + r0g + 8) * DD + c] = lp;
    }
}

// ---------------------------------------------------------------------------
extern "C" void kernel_launch(void* const* d_in, const int* in_sizes, int n_in,
                              void* d_out, int out_size)
{
    const float* inputs = (const float*)d_in[0];
    const int*   mask   = (const int*)  d_in[1];
    const float* W1     = (const float*)d_in[2];
    const float* b1     = (const float*)d_in[3];
    const float* W2     = (const float*)d_in[4];
    const float* b2     = (const float*)d_in[5];
    float* out = (float*)d_out;

    __nv_bfloat16 *xh, *xl, *w1h, *w1l, *w2h, *w2l, *qh, *ql, *ch, *cl;
    cudaGetSymbolAddress((void**)&xh,  g_xh);  cudaGetSymbolAddress((void**)&xl,  g_xl);
    cudaGetSymbolAddress((void**)&w1h, g_w1h); cudaGetSymbolAddress((void**)&w1l, g_w1l);
    cudaGetSymbolAddress((void**)&w2h, g_w2h); cudaGetSymbolAddress((void**)&w2l, g_w2l);
    cudaGetSymbolAddress((void**)&qh,  g_qh);  cudaGetSymbolAddress((void**)&ql,  g_ql);
    cudaGetSymbolAddress((void**)&ch,  g_ch);  cudaGetSymbolAddress((void**)&cl,  g_cl);

    cudaFuncSetAttribute(gemm_bf16x3<true>,
                         cudaFuncAttributeMaxDynamicSharedMemorySize, GEMM_SMEM_BYTES);
    cudaFuncSetAttribute(gemm_bf16x3<false>,
                         cudaFuncAttributeMaxDynamicSharedMemorySize, GEMM_SMEM_BYTES);
    cudaFuncSetAttribute(attn_bf16x3,
                         cudaFuncAttributeMaxDynamicSharedMemorySize, ATTN_SMEM_BYTES);

    // 0) split fp32 -> bf16 hi/lo planes
    {
        int nx = NROWS*DD/4, n1 = DD*D3/4, n2 = DD*DD/4;
        split_kernel<<<(nx+255)/256, 256>>>(inputs, xh, xl, nx);
        split_kernel<<<(n1+255)/256, 256>>>(W1, w1h, w1l, n1);
        split_kernel<<<(n2+255)/256, 256>>>(W2, w2h, w2l, n2);
    }
    // 1) QKV projection -> qkv hi/lo planes
    {
        dim3 grid(D3/128, NROWS/128);
        gemm_bf16x3<true><<<grid, 256, GEMM_SMEM_BYTES>>>(
            xh, xl, w1h, w1l, b1, nullptr, qh, ql, NROWS, D3, DD);
    }
    // 2) fused masked attention -> ctx hi/lo planes
    {
        dim3 grid(LL/128, BB*HH);
        attn_bf16x3<<<grid, 256, ATTN_SMEM_BYTES>>>(qh, ql, mask, ch, cl);
    }
    // 3) output projection -> fp32 out
    {
        dim3 grid(DD/128, NROWS/128);
        gemm_bf16x3<false><<<grid, 256, GEMM_SMEM_BYTES>>>(
            ch, cl, w2h, w2l, b2, out, nullptr, nullptr, NROWS, DD, DD);
    }
}

// round 5
// speedup vs baseline: 2.2900x; 1.0246x over previous
#include <cuda_runtime.h>
#include <cuda_bf16.h>
#include <cstdint>

#define BB 4
#define LL 2048
#define DD 1024
#define HH 16
#define NROWS (BB*LL)
#define D3 (3*DD)

// ---------------- persistent scratch (allocation-free) ----------------------
__device__ __nv_bfloat16 g_xh[(size_t)NROWS*DD],  g_xl[(size_t)NROWS*DD];
__device__ __nv_bfloat16 g_w1h[(size_t)DD*D3],    g_w1l[(size_t)DD*D3];
__device__ __nv_bfloat16 g_w2h[(size_t)DD*DD],    g_w2l[(size_t)DD*DD];
__device__ __nv_bfloat16 g_qh[(size_t)NROWS*D3],  g_ql[(size_t)NROWS*D3];
__device__ __nv_bfloat16 g_ch[(size_t)NROWS*DD],  g_cl[(size_t)NROWS*DD];
__device__ uint32_t      g_pm[(size_t)BB*LL*(LL/32)];   // packed mask bits

// ---------------- helpers ---------------------------------------------------
__device__ __forceinline__ float fexp2(float x) {
    float y; asm("ex2.approx.ftz.f32 %0, %1;" : "=f"(y) : "f"(x)); return y;
}
__device__ __forceinline__ void cp_async16(void* smem_dst, const void* gmem_src) {
    uint32_t s = (uint32_t)__cvta_generic_to_shared(smem_dst);
    asm volatile("cp.async.cg.shared.global [%0], [%1], 16;\n" :: "r"(s), "l"(gmem_src));
}
#define CP_COMMIT() asm volatile("cp.async.commit_group;\n" ::: "memory")
#define CP_WAIT2()  asm volatile("cp.async.wait_group 2;\n" ::: "memory")
#define CP_WAIT1()  asm volatile("cp.async.wait_group 1;\n" ::: "memory")
#define CP_WAIT0()  asm volatile("cp.async.wait_group 0;\n" ::: "memory")

__device__ __forceinline__ uint32_t su32(const void* p) {
    return (uint32_t)__cvta_generic_to_shared(p);
}
__device__ __forceinline__ uint32_t packbf(float x, float y) {
    uint32_t r;
    asm("cvt.rn.satfinite.bf16x2.f32 %0, %1, %2;" : "=r"(r) : "f"(y), "f"(x));
    return r;
}
__device__ __forceinline__ void split_pair(float x, float y, uint32_t& hp, uint32_t& lp) {
    hp = packbf(x, y);
    float hx = __uint_as_float(hp << 16);
    float hy = __uint_as_float(hp & 0xffff0000u);
    lp = packbf(x - hx, y - hy);
}
__device__ __forceinline__ void mma_bf16(float c[4], const uint32_t a[4],
                                         uint32_t b0, uint32_t b1) {
    asm volatile(
        "mma.sync.aligned.m16n8k16.row.col.f32.bf16.bf16.f32 "
        "{%0,%1,%2,%3}, {%4,%5,%6,%7}, {%8,%9}, {%0,%1,%2,%3};\n"
        : "+f"(c[0]), "+f"(c[1]), "+f"(c[2]), "+f"(c[3])
        : "r"(a[0]), "r"(a[1]), "r"(a[2]), "r"(a[3]), "r"(b0), "r"(b1));
}
__device__ __forceinline__ void ldsm_x4(uint32_t r[4], uint32_t addr) {
    asm volatile("ldmatrix.sync.aligned.m8n8.x4.shared.b16 {%0,%1,%2,%3}, [%4];"
        : "=r"(r[0]), "=r"(r[1]), "=r"(r[2]), "=r"(r[3]) : "r"(addr));
}
__device__ __forceinline__ void ldsm_x4_t(uint32_t r[4], uint32_t addr) {
    asm volatile("ldmatrix.sync.aligned.m8n8.x4.trans.shared.b16 {%0,%1,%2,%3}, [%4];"
        : "=r"(r[0]), "=r"(r[1]), "=r"(r[2]), "=r"(r[3]) : "r"(addr));
}

// ---------------- pre-pass kernels ------------------------------------------
__global__ void split_kernel(const float* __restrict__ src,
                             __nv_bfloat16* __restrict__ h,
                             __nv_bfloat16* __restrict__ l, int n4) {
    int i = blockIdx.x * 256 + threadIdx.x;
    if (i >= n4) return;
    float4 v = ((const float4*)src)[i];
    uint32_t h0, l0, h1, l1;
    split_pair(v.x, v.y, h0, l0);
    split_pair(v.z, v.w, h1, l1);
    ((uint2*)h)[i] = make_uint2(h0, h1);
    ((uint2*)l)[i] = make_uint2(l0, l1);
}

// pack mask!=0 into bits (little-endian within word)
__global__ void pack_mask_kernel(const int* __restrict__ m, uint32_t* __restrict__ pm,
                                 int nwords) {
    int i = blockIdx.x * 256 + threadIdx.x;
    if (i >= nwords) return;
    const int4* src = (const int4*)m + (size_t)i * 8;
    uint32_t w = 0;
    #pragma unroll
    for (int j = 0; j < 8; j++) {
        int4 v = src[j];
        w |= (v.x != 0 ? 1u : 0u) << (4*j);
        w |= (v.y != 0 ? 1u : 0u) << (4*j + 1);
        w |= (v.z != 0 ? 1u : 0u) << (4*j + 2);
        w |= (v.w != 0 ? 1u : 0u) << (4*j + 3);
    }
    pm[i] = w;
}

// ---------------------------------------------------------------------------
// bf16x3 GEMM, 4-stage cp.async pipeline, ONE barrier per k-tile.
// 128x128x32 tile, 256 threads (8 warps 4x2), warp tile 32x64.
// Stage layout (37888 B): AsH[128][40] | AsL | BsH[32][136] | BsL
// ---------------------------------------------------------------------------
#define GSTAGES 4
#define GSTAGE_BYTES 37888
#define GEMM_SMEM_BYTES (GSTAGES * GSTAGE_BYTES)   // 151552

template<bool SPLIT_OUT>
__global__ __launch_bounds__(256, 1)
void gemm_bf16x3(const __nv_bfloat16* __restrict__ Ah, const __nv_bfloat16* __restrict__ Al,
                 const __nv_bfloat16* __restrict__ Wh, const __nv_bfloat16* __restrict__ Wl,
                 const float* __restrict__ bias, float* __restrict__ Cf,
                 __nv_bfloat16* __restrict__ Ch, __nv_bfloat16* __restrict__ Cl,
                 int M, int N, int K)
{
    extern __shared__ __align__(16) char smem_raw[];

    const int tid  = threadIdx.x;
    const int warp = tid >> 5, lane = tid & 31;
    const int g = lane >> 2, t = lane & 3;
    const int wr = (warp >> 1) * 32;
    const int wc = (warp & 1) * 64;
    const int row0 = blockIdx.y * 128;
    const int col0 = blockIdx.x * 128;
    const int ntiles = K / 32;

    const int a_m = tid >> 1;
    const int a_c = (tid & 1) * 2;
    const int b_k = tid >> 3;
    const int b_c = tid & 7;

    auto load_tile = [&](int kt, int slot) {
        char* sb = smem_raw + slot * GSTAGE_BYTES;
        __nv_bfloat16* AsH = (__nv_bfloat16*)sb;
        __nv_bfloat16* AsL = (__nv_bfloat16*)(sb + 10240);
        __nv_bfloat16* BsH = (__nv_bfloat16*)(sb + 20480);
        __nv_bfloat16* BsL = (__nv_bfloat16*)(sb + 29184);
        const __nv_bfloat16* ah = Ah + (size_t)(row0 + a_m) * K + kt*32;
        const __nv_bfloat16* al = Al + (size_t)(row0 + a_m) * K + kt*32;
        #pragma unroll
        for (int c = 0; c < 2; c++) {
            cp_async16(&AsH[a_m*40 + (a_c + c)*8], ah + (a_c + c)*8);
            cp_async16(&AsL[a_m*40 + (a_c + c)*8], al + (a_c + c)*8);
        }
        const __nv_bfloat16* wh = Wh + (size_t)(kt*32 + b_k) * N + col0;
        const __nv_bfloat16* wl = Wl + (size_t)(kt*32 + b_k) * N + col0;
        #pragma unroll
        for (int c = 0; c < 2; c++) {
            cp_async16(&BsH[b_k*136 + (b_c + 8*c)*8], wh + (b_c + 8*c)*8);
            cp_async16(&BsL[b_k*136 + (b_c + 8*c)*8], wl + (b_c + 8*c)*8);
        }
    };

    float acc[2][8][4];
    #pragma unroll
    for (int mi = 0; mi < 2; mi++)
        #pragma unroll
        for (int ni = 0; ni < 8; ni++)
            #pragma unroll
            for (int j = 0; j < 4; j++) acc[mi][ni][j] = 0.0f;

    #pragma unroll
    for (int s = 0; s < GSTAGES-1; s++) { load_tile(s, s); CP_COMMIT(); }

    const int a_row = (lane & 15);
    const int a_col = (lane >> 4) << 3;
    const int b_row = (lane & 15);
    const int b_col = (lane >> 4) << 3;

    for (int kt = 0; kt < ntiles; kt++) {
        // wait until stage kt landed: allowed pending = min(GSTAGES-2, ntiles-1-kt)
        if (kt < ntiles - 2)      CP_WAIT2();
        else if (kt == ntiles-2)  CP_WAIT1();
        else                      CP_WAIT0();
        __syncthreads();

        if (kt + GSTAGES - 1 < ntiles) {
            load_tile(kt + GSTAGES - 1, (kt + GSTAGES - 1) % GSTAGES);
            CP_COMMIT();
        }

        char* sb = smem_raw + (kt % GSTAGES) * GSTAGE_BYTES;
        const __nv_bfloat16* AsH = (const __nv_bfloat16*)sb;
        const __nv_bfloat16* AsL = (const __nv_bfloat16*)(sb + 10240);
        const __nv_bfloat16* BsH = (const __nv_bfloat16*)(sb + 20480);
        const __nv_bfloat16* BsL = (const __nv_bfloat16*)(sb + 29184);

        #pragma unroll
        for (int ks = 0; ks < 2; ks++) {
            const int k0 = ks * 16;
            uint32_t aH[2][4], aL[2][4];
            #pragma unroll
            for (int mi = 0; mi < 2; mi++) {
                ldsm_x4(aH[mi], su32(AsH + (wr + mi*16 + a_row)*40 + k0 + a_col));
                ldsm_x4(aL[mi], su32(AsL + (wr + mi*16 + a_row)*40 + k0 + a_col));
            }
            #pragma unroll
            for (int njp = 0; njp < 4; njp++) {
                const int n0 = wc + njp * 16;
                uint32_t bH[4], bL[4];
                ldsm_x4_t(bH, su32(BsH + (k0 + b_row)*136 + n0 + b_col));
                ldsm_x4_t(bL, su32(BsL + (k0 + b_row)*136 + n0 + b_col));
                #pragma unroll
                for (int mi = 0; mi < 2; mi++) {
                    mma_bf16(acc[mi][2*njp],   aH[mi], bH[0], bH[1]);
                    mma_bf16(acc[mi][2*njp],   aH[mi], bL[0], bL[1]);
                    mma_bf16(acc[mi][2*njp],   aL[mi], bH[0], bH[1]);
                    mma_bf16(acc[mi][2*njp+1], aH[mi], bH[2], bH[3]);
                    mma_bf16(acc[mi][2*njp+1], aH[mi], bL[2], bL[3]);
                    mma_bf16(acc[mi][2*njp+1], aL[mi], bH[2], bH[3]);
                }
            }
        }
    }

    #pragma unroll
    for (int mi = 0; mi < 2; mi++) {
        const int r = row0 + wr + mi*16 + g;
        #pragma unroll
        for (int ni = 0; ni < 8; ni++) {
            const int c = col0 + wc + ni*8 + 2*t;
            float2 bb = *(const float2*)&bias[c];
            float v0 = acc[mi][ni][0] + bb.x, v1 = acc[mi][ni][1] + bb.y;
            float v2 = acc[mi][ni][2] + bb.x, v3 = acc[mi][ni][3] + bb.y;
            if (SPLIT_OUT) {
                uint32_t hp, lp;
                split_pair(v0, v1, hp, lp);
                *(uint32_t*)&Ch[(size_t)r * N + c] = hp;
                *(uint32_t*)&Cl[(size_t)r * N + c] = lp;
                split_pair(v2, v3, hp, lp);
                *(uint32_t*)&Ch[(size_t)(r + 8) * N + c] = hp;
                *(uint32_t*)&Cl[(size_t)(r + 8) * N + c] = lp;
            } else {
                *(float2*)&Cf[(size_t)r * N + c]       = make_float2(v0, v1);
                *(float2*)&Cf[(size_t)(r + 8) * N + c] = make_float2(v2, v3);
            }
        }
    }
}

// ---------------------------------------------------------------------------
// Fused masked flash attention, bf16x3, 3-stage KV pipeline, packed mask.
// 256 thr / 8 warps; warp w owns query rows [16w,16w+16). BM=128, BN=64, DK=64.
// Stage (36864 B): KsH[64][72] | KsL | VsH | VsL.
// Masked score -> 0.0 (in max + denominator), attn weight zeroed for PV.
// ---------------------------------------------------------------------------
#define KV_PAD 72
#define ASTAGES 3
#define ASTAGE_BYTES 36864
#define ATTN_SMEM_BYTES (ASTAGES * ASTAGE_BYTES)   // 110592

__global__ __launch_bounds__(256, 1)
void attn_bf16x3(const __nv_bfloat16* __restrict__ qh, const __nv_bfloat16* __restrict__ ql,
                 const uint32_t* __restrict__ pm,
                 __nv_bfloat16* __restrict__ cth, __nv_bfloat16* __restrict__ ctl)
{
    extern __shared__ __align__(16) char smem_raw[];

    const int tid  = threadIdx.x;
    const int warp = tid >> 5, lane = tid & 31;
    const int g = lane >> 2, t = lane & 3;
    const int b  = blockIdx.y >> 4;
    const int h  = blockIdx.y & 15;
    const int q0 = blockIdx.x * 128;

    const size_t rowbase = (size_t)b * LL;
    const uint32_t* pmb = pm + (size_t)b * LL * (LL/32);

    // ---- stage Q planes (into stage-0 area), extract A-fragments -----------
    {
        __nv_bfloat16* QstH = (__nv_bfloat16*)smem_raw;
        __nv_bfloat16* QstL = (__nv_bfloat16*)(smem_raw + 18432);
        #pragma unroll
        for (int p = 0; p < 4; p++) {
            int idx = p * 256 + tid;
            int r   = idx >> 3;
            int ch  = (idx & 7) * 8;
            size_t src = (rowbase + q0 + r) * (size_t)D3 + h*64 + ch;
            cp_async16(&QstH[r*KV_PAD + ch], qh + src);
            cp_async16(&QstL[r*KV_PAD + ch], ql + src);
        }
        CP_COMMIT();
        CP_WAIT0();
        __syncthreads();
    }

    uint32_t aqH[4][4], aqL[4][4];
    {
        const __nv_bfloat16* QstH = (const __nv_bfloat16*)smem_raw;
        const __nv_bfloat16* QstL = (const __nv_bfloat16*)(smem_raw + 18432);
        const int r = warp*16 + (lane & 15);
        const int cofs = (lane >> 4) << 3;
        #pragma unroll
        for (int kb = 0; kb < 4; kb++) {
            ldsm_x4(aqH[kb], su32(QstH + r*KV_PAD + kb*16 + cofs));
            ldsm_x4(aqL[kb], su32(QstL + r*KV_PAD + kb*16 + cofs));
        }
    }
    __syncthreads();   // stage-0 area free for KV

    // ---- KV pipeline --------------------------------------------------------
    const int kv_r = tid >> 2;
    const int kv_c = (tid & 3) * 2;

    auto load_kv = [&](int tile, int slot) {
        char* sb = smem_raw + slot * ASTAGE_BYTES;
        __nv_bfloat16* KsH = (__nv_bfloat16*)sb;
        __nv_bfloat16* KsL = (__nv_bfloat16*)(sb + 9216);
        __nv_bfloat16* VsH = (__nv_bfloat16*)(sb + 18432);
        __nv_bfloat16* VsL = (__nv_bfloat16*)(sb + 27648);
        const int k0 = tile * 64;
        size_t base = (rowbase + k0 + kv_r) * (size_t)D3 + h*64;
        #pragma unroll
        for (int c = 0; c < 2; c++) {
            int ch = (kv_c + c) * 8;
            cp_async16(&KsH[kv_r*KV_PAD + ch], qh + base + 1024 + ch);
            cp_async16(&KsL[kv_r*KV_PAD + ch], ql + base + 1024 + ch);
            cp_async16(&VsH[kv_r*KV_PAD + ch], qh + base + 2048 + ch);
            cp_async16(&VsL[kv_r*KV_PAD + ch], ql + base + 2048 + ch);
        }
    };

    load_kv(0, 0); CP_COMMIT();
    load_kv(1, 1); CP_COMMIT();

    float oc[8][4];
    #pragma unroll
    for (int ni = 0; ni < 8; ni++)
        #pragma unroll
        for (int j = 0; j < 4; j++) oc[ni][j] = 0.0f;
    float mi0 = -1e30f, mi1 = -1e30f, li0 = 0.0f, li1 = 0.0f;

    const float cs = 0.18033688011112042f;  // log2(e)/sqrt(64)
    const int r0g = q0 + warp*16 + g;
    const int NT  = LL / 64;

    const int k_key = ((lane & 16) ? 8 : 0) + (lane & 7);
    const int k_dim = (lane & 8) ? 8 : 0;
    const int v_row = lane;

    for (int tt = 0; tt < NT; tt++) {
        const int k0 = tt * 64;
        if (tt < NT - 1) CP_WAIT1(); else CP_WAIT0();
        __syncthreads();

        if (tt + 2 < NT) {
            load_kv(tt + 2, (tt + 2) % ASTAGES);
            CP_COMMIT();
        }

        char* sb = smem_raw + (tt % ASTAGES) * ASTAGE_BYTES;
        const __nv_bfloat16* KsH = (const __nv_bfloat16*)sb;
        const __nv_bfloat16* KsL = (const __nv_bfloat16*)(sb + 9216);
        const __nv_bfloat16* VsH = (const __nv_bfloat16*)(sb + 18432);
        const __nv_bfloat16* VsL = (const __nv_bfloat16*)(sb + 27648);

        // ---- S = Q @ K^T ----------------------------------------------------
        float sc[8][4];
        #pragma unroll
        for (int ni = 0; ni < 8; ni++)
            #pragma unroll
            for (int j = 0; j < 4; j++) sc[ni][j] = 0.0f;

        #pragma unroll
        for (int kb = 0; kb < 4; kb++) {
            #pragma unroll
            for (int njp = 0; njp < 4; njp++) {
                uint32_t kH[4], kL[4];
                ldsm_x4(kH, su32(KsH + (njp*16 + k_key)*KV_PAD + kb*16 + k_dim));
                ldsm_x4(kL, su32(KsL + (njp*16 + k_key)*KV_PAD + kb*16 + k_dim));
                mma_bf16(sc[2*njp],   aqH[kb], kH[0], kH[1]);
                mma_bf16(sc[2*njp],   aqH[kb], kL[0], kL[1]);
                mma_bf16(sc[2*njp],   aqL[kb], kH[0], kH[1]);
                mma_bf16(sc[2*njp+1], aqH[kb], kH[2], kH[3]);
                mma_bf16(sc[2*njp+1], aqH[kb], kL[2], kL[3]);
                mma_bf16(sc[2*njp+1], aqL[kb], kH[2], kH[3]);
            }
        }

        // ---- packed mask + online softmax (log2 domain) ---------------------
        const uint32_t* pr0 = pmb + (size_t)r0g * 64 + (k0 >> 5);
        const uint32_t* pr1 = pmb + (size_t)(r0g + 8) * 64 + (k0 >> 5);
        uint64_t m0 = (uint64_t)pr0[0] | ((uint64_t)pr0[1] << 32);
        uint64_t m1 = (uint64_t)pr1[0] | ((uint64_t)pr1[1] << 32);

        float tm0 = -1e30f, tm1 = -1e30f;
        uint32_t keep[8];
        #pragma unroll
        for (int ni = 0; ni < 8; ni++) {
            const int bit = ni*8 + 2*t;
            uint32_t p0 = (uint32_t)(m0 >> bit) & 3u;
            uint32_t p1 = (uint32_t)(m1 >> bit) & 3u;
            keep[ni] = p0 | (p1 << 2);
            sc[ni][0] = (p0 & 1) ? sc[ni][0]*cs : 0.0f;
            sc[ni][1] = (p0 & 2) ? sc[ni][1]*cs : 0.0f;
            sc[ni][2] = (p1 & 1) ? sc[ni][2]*cs : 0.0f;
            sc[ni][3] = (p1 & 2) ? sc[ni][3]*cs : 0.0f;
            tm0 = fmaxf(tm0, fmaxf(sc[ni][0], sc[ni][1]));
            tm1 = fmaxf(tm1, fmaxf(sc[ni][2], sc[ni][3]));
        }
        tm0 = fmaxf(tm0, __shfl_xor_sync(0xffffffffu, tm0, 1));
        tm0 = fmaxf(tm0, __shfl_xor_sync(0xffffffffu, tm0, 2));
        tm1 = fmaxf(tm1, __shfl_xor_sync(0xffffffffu, tm1, 1));
        tm1 = fmaxf(tm1, __shfl_xor_sync(0xffffffffu, tm1, 2));

        const float mn0 = fmaxf(mi0, tm0);
        const float mn1 = fmaxf(mi1, tm1);
        const float s0  = fexp2(mi0 - mn0);
        const float s1  = fexp2(mi1 - mn1);
        mi0 = mn0; mi1 = mn1;

        float sum0 = 0.0f, sum1 = 0.0f;
        #pragma unroll
        for (int ni = 0; ni < 8; ni++) {
            float e0 = fexp2(sc[ni][0] - mn0);
            float e1 = fexp2(sc[ni][1] - mn0);
            float e2 = fexp2(sc[ni][2] - mn1);
            float e3 = fexp2(sc[ni][3] - mn1);
            sum0 += e0 + e1;
            sum1 += e2 + e3;
            sc[ni][0] = (keep[ni] & 1) ? e0 : 0.0f;
            sc[ni][1] = (keep[ni] & 2) ? e1 : 0.0f;
            sc[ni][2] = (keep[ni] & 4) ? e2 : 0.0f;
            sc[ni][3] = (keep[ni] & 8) ? e3 : 0.0f;
        }
        sum0 += __shfl_xor_sync(0xffffffffu, sum0, 1);
        sum0 += __shfl_xor_sync(0xffffffffu, sum0, 2);
        sum1 += __shfl_xor_sync(0xffffffffu, sum1, 1);
        sum1 += __shfl_xor_sync(0xffffffffu, sum1, 2);
        li0 = li0 * s0 + sum0;
        li1 = li1 * s1 + sum1;

        #pragma unroll
        for (int ni = 0; ni < 8; ni++) {
            oc[ni][0] *= s0; oc[ni][1] *= s0;
            oc[ni][2] *= s1; oc[ni][3] *= s1;
        }

        // ---- O += P @ V (P repacked in registers) ---------------------------
        #pragma unroll
        for (int kb2 = 0; kb2 < 2; kb2++) {
            uint32_t apH[2][4], apL[2][4];
            #pragma unroll
            for (int kk = 0; kk < 2; kk++) {
                const int kbi = kb2*2 + kk;
                split_pair(sc[2*kbi][0],   sc[2*kbi][1],   apH[kk][0], apL[kk][0]);
                split_pair(sc[2*kbi][2],   sc[2*kbi][3],   apH[kk][1], apL[kk][1]);
                split_pair(sc[2*kbi+1][0], sc[2*kbi+1][1], apH[kk][2], apL[kk][2]);
                split_pair(sc[2*kbi+1][2], sc[2*kbi+1][3], apH[kk][3], apL[kk][3]);
            }
            #pragma unroll
            for (int nj = 0; nj < 8; nj++) {
                uint32_t vH[4], vL[4];
                ldsm_x4_t(vH, su32(VsH + (kb2*32 + v_row)*KV_PAD + nj*8));
                ldsm_x4_t(vL, su32(VsL + (kb2*32 + v_row)*KV_PAD + nj*8));
                mma_bf16(oc[nj], apH[0], vH[0], vH[1]);
                mma_bf16(oc[nj], apH[0], vL[0], vL[1]);
                mma_bf16(oc[nj], apL[0], vH[0], vH[1]);
                mma_bf16(oc[nj], apH[1], vH[2], vH[3]);
                mma_bf16(oc[nj], apH[1], vL[2], vL[3]);
                mma_bf16(oc[nj], apL[1], vH[2], vH[3]);
            }
        }
    }

    // ---- epilogue -----------------------------------------------------------
    const float inv0 = 1.0f / li0;
    const float inv1 = 1.0f / li1;
    #pragma unroll
    for (int ni = 0; ni < 8; ni++) {
        const int c = h*64 + ni*8 + 2*t;
        uint32_t hp, lp;
        split_pair(oc[ni][0]*inv0, oc[ni][1]*inv0, hp, lp);
        *(uint32_t*)&cth[(rowbase + r0g) * DD + c] = hp;
        *(uint32_t*)&ctl[(rowbase + r0g) * DD + c] = lp;
        split_pair(oc[ni][2]*inv1, oc[ni][3]*inv1, hp, lp);
        *(uint32_t*)&cth[(rowbase + r0g + 8) * DD + c] = hp;
        *(uint32_t*)&ctl[(rowbase + r0g + 8) * DD + c] = lp;
    }
}

// ---------------------------------------------------------------------------
extern "C" void kernel_launch(void* const* d_in, const int* in_sizes, int n_in,
                              void* d_out, int out_size)
{
    const float* inputs = (const float*)d_in[0];
    const int*   mask   = (const int*)  d_in[1];
    const float* W1     = (const float*)d_in[2];
    const float* b1     = (const float*)d_in[3];
    const float* W2     = (const float*)d_in[4];
    const float* b2     = (const float*)d_in[5];
    float* out = (float*)d_out;

    __nv_bfloat16 *xh, *xl, *w1h, *w1l, *w2h, *w2l, *qh, *ql, *ch, *cl;
    uint32_t* pmm;
    cudaGetSymbolAddress((void**)&xh,  g_xh);  cudaGetSymbolAddress((void**)&xl,  g_xl);
    cudaGetSymbolAddress((void**)&w1h, g_w1h); cudaGetSymbolAddress((void**)&w1l, g_w1l);
    cudaGetSymbolAddress((void**)&w2h, g_w2h); cudaGetSymbolAddress((void**)&w2l, g_w2l);
    cudaGetSymbolAddress((void**)&qh,  g_qh);  cudaGetSymbolAddress((void**)&ql,  g_ql);
    cudaGetSymbolAddress((void**)&ch,  g_ch);  cudaGetSymbolAddress((void**)&cl,  g_cl);
    cudaGetSymbolAddress((void**)&pmm, g_pm);

    cudaFuncSetAttribute(gemm_bf16x3<true>,
                         cudaFuncAttributeMaxDynamicSharedMemorySize, GEMM_SMEM_BYTES);
    cudaFuncSetAttribute(gemm_bf16x3<false>,
                         cudaFuncAttributeMaxDynamicSharedMemorySize, GEMM_SMEM_BYTES);
    cudaFuncSetAttribute(attn_bf16x3,
                         cudaFuncAttributeMaxDynamicSharedMemorySize, ATTN_SMEM_BYTES);

    // 0) pre-passes: splits + mask bit-pack
    {
        int nx = NROWS*DD/4, n1 = DD*D3/4, n2 = DD*DD/4;
        split_kernel<<<(nx+255)/256, 256>>>(inputs, xh, xl, nx);
        split_kernel<<<(n1+255)/256, 256>>>(W1, w1h, w1l, n1);
        split_kernel<<<(n2+255)/256, 256>>>(W2, w2h, w2l, n2);
        int nw = BB*LL*(LL/32);
        pack_mask_kernel<<<(nw+255)/256, 256>>>(mask, pmm, nw);
    }
    // 1) QKV projection -> qkv hi/lo planes
    {
        dim3 grid(D3/128, NROWS/128);
        gemm_bf16x3<true><<<grid, 256, GEMM_SMEM_BYTES>>>(
            xh, xl, w1h, w1l, b1, nullptr, qh, ql, NROWS, D3, DD);
    }
    // 2) fused masked attention -> ctx hi/lo planes
    {
        dim3 grid(LL/128, BB*HH);
        attn_bf16x3<<<grid, 256, ATTN_SMEM_BYTES>>>(qh, ql, pmm, ch, cl);
    }
    // 3) output projection -> fp32 out
    {
        dim3 grid(DD/128, NROWS/128);
        gemm_bf16x3<false><<<grid, 256, GEMM_SMEM_BYTES>>>(
            ch, cl, w2h, w2l, b2, out, nullptr, nullptr, NROWS, DD, DD);
    }
}

// round 7
// speedup vs baseline: 2.3594x; 1.0303x over previous
#include <cuda_runtime.h>
#include <cuda_bf16.h>
#include <cstdint>

#define BB 4
#define LL 2048
#define DD 1024
#define HH 16
#define NROWS (BB*LL)
#define D3 (3*DD)

// ---------------- persistent scratch (allocation-free) ----------------------
__device__ __nv_bfloat16 g_xh[(size_t)NROWS*DD],  g_xl[(size_t)NROWS*DD];
__device__ __nv_bfloat16 g_w1h[(size_t)DD*D3],    g_w1l[(size_t)DD*D3];
__device__ __nv_bfloat16 g_w2h[(size_t)DD*DD],    g_w2l[(size_t)DD*DD];
__device__ __nv_bfloat16 g_qh[(size_t)NROWS*D3],  g_ql[(size_t)NROWS*D3];
__device__ __nv_bfloat16 g_ch[(size_t)NROWS*DD],  g_cl[(size_t)NROWS*DD];
__device__ uint32_t      g_pm[(size_t)BB*LL*(LL/32)];   // packed mask bits

// ---------------- helpers ---------------------------------------------------
__device__ __forceinline__ float fexp2(float x) {
    float y; asm("ex2.approx.ftz.f32 %0, %1;" : "=f"(y) : "f"(x)); return y;
}
__device__ __forceinline__ void cp_async16(void* smem_dst, const void* gmem_src) {
    uint32_t s = (uint32_t)__cvta_generic_to_shared(smem_dst);
    asm volatile("cp.async.cg.shared.global [%0], [%1], 16;\n" :: "r"(s), "l"(gmem_src));
}
#define CP_COMMIT() asm volatile("cp.async.commit_group;\n" ::: "memory")
#define CP_WAIT2()  asm volatile("cp.async.wait_group 2;\n" ::: "memory")
#define CP_WAIT1()  asm volatile("cp.async.wait_group 1;\n" ::: "memory")
#define CP_WAIT0()  asm volatile("cp.async.wait_group 0;\n" ::: "memory")

__device__ __forceinline__ uint32_t su32(const void* p) {
    return (uint32_t)__cvta_generic_to_shared(p);
}
__device__ __forceinline__ uint32_t packbf(float x, float y) {
    uint32_t r;
    asm("cvt.rn.satfinite.bf16x2.f32 %0, %1, %2;" : "=r"(r) : "f"(y), "f"(x));
    return r;
}
__device__ __forceinline__ void split_pair(float x, float y, uint32_t& hp, uint32_t& lp) {
    hp = packbf(x, y);
    float hx = __uint_as_float(hp << 16);
    float hy = __uint_as_float(hp & 0xffff0000u);
    lp = packbf(x - hx, y - hy);
}
__device__ __forceinline__ void mma_bf16(float c[4], const uint32_t a[4],
                                         uint32_t b0, uint32_t b1) {
    asm volatile(
        "mma.sync.aligned.m16n8k16.row.col.f32.bf16.bf16.f32 "
        "{%0,%1,%2,%3}, {%4,%5,%6,%7}, {%8,%9}, {%0,%1,%2,%3};\n"
        : "+f"(c[0]), "+f"(c[1]), "+f"(c[2]), "+f"(c[3])
        : "r"(a[0]), "r"(a[1]), "r"(a[2]), "r"(a[3]), "r"(b0), "r"(b1));
}
__device__ __forceinline__ void ldsm_x4(uint32_t r[4], uint32_t addr) {
    asm volatile("ldmatrix.sync.aligned.m8n8.x4.shared.b16 {%0,%1,%2,%3}, [%4];"
        : "=r"(r[0]), "=r"(r[1]), "=r"(r[2]), "=r"(r[3]) : "r"(addr));
}
__device__ __forceinline__ void ldsm_x4_t(uint32_t r[4], uint32_t addr) {
    asm volatile("ldmatrix.sync.aligned.m8n8.x4.trans.shared.b16 {%0,%1,%2,%3}, [%4];"
        : "=r"(r[0]), "=r"(r[1]), "=r"(r[2]), "=r"(r[3]) : "r"(addr));
}

// ---------------- pre-pass kernels ------------------------------------------
__global__ void split_kernel(const float* __restrict__ src,
                             __nv_bfloat16* __restrict__ h,
                             __nv_bfloat16* __restrict__ l, int n4) {
    int i = blockIdx.x * 256 + threadIdx.x;
    if (i >= n4) return;
    float4 v = ((const float4*)src)[i];
    uint32_t h0, l0, h1, l1;
    split_pair(v.x, v.y, h0, l0);
    split_pair(v.z, v.w, h1, l1);
    ((uint2*)h)[i] = make_uint2(h0, h1);
    ((uint2*)l)[i] = make_uint2(l0, l1);
}

__global__ void pack_mask_kernel(const int* __restrict__ m, uint32_t* __restrict__ pm,
                                 int nwords) {
    int i = blockIdx.x * 256 + threadIdx.x;
    if (i >= nwords) return;
    const int4* src = (const int4*)m + (size_t)i * 8;
    uint32_t w = 0;
    #pragma unroll
    for (int j = 0; j < 8; j++) {
        int4 v = src[j];
        w |= (v.x != 0 ? 1u : 0u) << (4*j);
        w |= (v.y != 0 ? 1u : 0u) << (4*j + 1);
        w |= (v.z != 0 ? 1u : 0u) << (4*j + 2);
        w |= (v.w != 0 ? 1u : 0u) << (4*j + 3);
    }
    pm[i] = w;
}

// ---------------------------------------------------------------------------
// bf16x3 GEMM, 512 threads (16 warps as 4x4, warp tile 32x32), 4-stage pipe.
// 128x128x32 tile. Stage (37888 B): AsH[128][40] | AsL | BsH[32][136] | BsL.
// ---------------------------------------------------------------------------
#define GSTAGES 4
#define GSTAGE_BYTES 37888
#define GEMM_SMEM_BYTES (GSTAGES * GSTAGE_BYTES)   // 151552

template<bool SPLIT_OUT>
__global__ __launch_bounds__(512, 1)
void gemm_bf16x3(const __nv_bfloat16* __restrict__ Ah, const __nv_bfloat16* __restrict__ Al,
                 const __nv_bfloat16* __restrict__ Wh, const __nv_bfloat16* __restrict__ Wl,
                 const float* __restrict__ bias, float* __restrict__ Cf,
                 __nv_bfloat16* __restrict__ Ch, __nv_bfloat16* __restrict__ Cl,
                 int M, int N, int K)
{
    extern __shared__ __align__(16) char smem_raw[];

    const int tid  = threadIdx.x;
    const int warp = tid >> 5, lane = tid & 31;
    const int g = lane >> 2, t = lane & 3;
    const int wr = (warp >> 2) * 32;       // 0,32,64,96
    const int wc = (warp & 3) * 32;        // 0,32,64,96
    const int row0 = blockIdx.y * 128;
    const int col0 = blockIdx.x * 128;
    const int ntiles = K / 32;

    const int a_m = tid >> 2;              // 0..127
    const int a_c = (tid & 3) * 8;         // bf16 offset
    const int b_k = tid >> 4;              // 0..31
    const int b_c = (tid & 15) * 8;        // bf16 offset

    auto load_tile = [&](int kt, int slot) {
        char* sb = smem_raw + slot * GSTAGE_BYTES;
        __nv_bfloat16* AsH = (__nv_bfloat16*)sb;
        __nv_bfloat16* AsL = (__nv_bfloat16*)(sb + 10240);
        __nv_bfloat16* BsH = (__nv_bfloat16*)(sb + 20480);
        __nv_bfloat16* BsL = (__nv_bfloat16*)(sb + 29184);
        const __nv_bfloat16* ah = Ah + (size_t)(row0 + a_m) * K + kt*32 + a_c;
        const __nv_bfloat16* al = Al + (size_t)(row0 + a_m) * K + kt*32 + a_c;
        cp_async16(&AsH[a_m*40 + a_c], ah);
        cp_async16(&AsL[a_m*40 + a_c], al);
        const __nv_bfloat16* wh = Wh + (size_t)(kt*32 + b_k) * N + col0 + b_c;
        const __nv_bfloat16* wl = Wl + (size_t)(kt*32 + b_k) * N + col0 + b_c;
        cp_async16(&BsH[b_k*136 + b_c], wh);
        cp_async16(&BsL[b_k*136 + b_c], wl);
    };

    float acc[2][4][4];
    #pragma unroll
    for (int mi = 0; mi < 2; mi++)
        #pragma unroll
        for (int ni = 0; ni < 4; ni++)
            #pragma unroll
            for (int j = 0; j < 4; j++) acc[mi][ni][j] = 0.0f;

    #pragma unroll
    for (int s = 0; s < GSTAGES-1; s++) { load_tile(s, s); CP_COMMIT(); }

    const int a_row = (lane & 15);
    const int a_col = (lane >> 4) << 3;
    const int b_row = (lane & 15);
    const int b_col = (lane >> 4) << 3;

    for (int kt = 0; kt < ntiles; kt++) {
        if (kt < ntiles - 2)      CP_WAIT2();
        else if (kt == ntiles-2)  CP_WAIT1();
        else                      CP_WAIT0();
        __syncthreads();

        if (kt + GSTAGES - 1 < ntiles) {
            load_tile(kt + GSTAGES - 1, (kt + GSTAGES - 1) % GSTAGES);
            CP_COMMIT();
        }

        char* sb = smem_raw + (kt % GSTAGES) * GSTAGE_BYTES;
        const __nv_bfloat16* AsH = (const __nv_bfloat16*)sb;
        const __nv_bfloat16* AsL = (const __nv_bfloat16*)(sb + 10240);
        const __nv_bfloat16* BsH = (const __nv_bfloat16*)(sb + 20480);
        const __nv_bfloat16* BsL = (const __nv_bfloat16*)(sb + 29184);

        #pragma unroll
        for (int ks = 0; ks < 2; ks++) {
            const int k0 = ks * 16;
            uint32_t aH[2][4], aL[2][4];
            #pragma unroll
            for (int mi = 0; mi < 2; mi++) {
                ldsm_x4(aH[mi], su32(AsH + (wr + mi*16 + a_row)*40 + k0 + a_col));
                ldsm_x4(aL[mi], su32(AsL + (wr + mi*16 + a_row)*40 + k0 + a_col));
            }
            #pragma unroll
            for (int njp = 0; njp < 2; njp++) {
                const int n0 = wc + njp * 16;
                uint32_t bH[4], bL[4];
                ldsm_x4_t(bH, su32(BsH + (k0 + b_row)*136 + n0 + b_col));
                ldsm_x4_t(bL, su32(BsL + (k0 + b_row)*136 + n0 + b_col));
                #pragma unroll
                for (int mi = 0; mi < 2; mi++) {
                    mma_bf16(acc[mi][2*njp],   aH[mi], bH[0], bH[1]);
                    mma_bf16(acc[mi][2*njp],   aH[mi], bL[0], bL[1]);
                    mma_bf16(acc[mi][2*njp],   aL[mi], bH[0], bH[1]);
                    mma_bf16(acc[mi][2*njp+1], aH[mi], bH[2], bH[3]);
                    mma_bf16(acc[mi][2*njp+1], aH[mi], bL[2], bL[3]);
                    mma_bf16(acc[mi][2*njp+1], aL[mi], bH[2], bH[3]);
                }
            }
        }
    }

    #pragma unroll
    for (int mi = 0; mi < 2; mi++) {
        const int r = row0 + wr + mi*16 + g;
        #pragma unroll
        for (int ni = 0; ni < 4; ni++) {
            const int c = col0 + wc + ni*8 + 2*t;
            float2 bb = *(const float2*)&bias[c];
            float v0 = acc[mi][ni][0] + bb.x, v1 = acc[mi][ni][1] + bb.y;
            float v2 = acc[mi][ni][2] + bb.x, v3 = acc[mi][ni][3] + bb.y;
            if (SPLIT_OUT) {
                uint32_t hp, lp;
                split_pair(v0, v1, hp, lp);
                *(uint32_t*)&Ch[(size_t)r * N + c] = hp;
                *(uint32_t*)&Cl[(size_t)r * N + c] = lp;
                split_pair(v2, v3, hp, lp);
                *(uint32_t*)&Ch[(size_t)(r + 8) * N + c] = hp;
                *(uint32_t*)&Cl[(size_t)(r + 8) * N + c] = lp;
            } else {
                *(float2*)&Cf[(size_t)r * N + c]       = make_float2(v0, v1);
                *(float2*)&Cf[(size_t)(r + 8) * N + c] = make_float2(v2, v3);
            }
        }
    }
}

// ---------------------------------------------------------------------------
// Fused masked flash attention, bf16x3, 512 threads / 16 warps, BM=256.
// Warp w owns query rows [16w,16w+16). BN=64, DK=64. Q hi/lo persistent in
// smem (re-ldsm'd per tile, keeps regs < 128). 3-stage KV pipeline.
// Smem: KV stages [0,110592) | QstH [110592,147456) | QstL [147456,184320).
// Masked score -> 0.0 (in max + denominator), attn weight zeroed for PV.
// ---------------------------------------------------------------------------
#define KV_PAD 72
#define ASTAGES 3
#define ASTAGE_BYTES 36864
#define QST_OFF (ASTAGES * ASTAGE_BYTES)                 // 110592
#define ATTN_SMEM_BYTES (QST_OFF + 2*256*KV_PAD*2)       // 184320

__global__ __launch_bounds__(512, 1)
void attn_bf16x3(const __nv_bfloat16* __restrict__ qh, const __nv_bfloat16* __restrict__ ql,
                 const uint32_t* __restrict__ pm,
                 __nv_bfloat16* __restrict__ cth, __nv_bfloat16* __restrict__ ctl)
{
    extern __shared__ __align__(16) char smem_raw[];
    __nv_bfloat16* QstH = (__nv_bfloat16*)(smem_raw + QST_OFF);
    __nv_bfloat16* QstL = (__nv_bfloat16*)(smem_raw + QST_OFF + 256*KV_PAD*2);

    const int tid  = threadIdx.x;
    const int warp = tid >> 5, lane = tid & 31;
    const int g = lane >> 2, t = lane & 3;
    const int b  = blockIdx.y >> 4;
    const int h  = blockIdx.y & 15;
    const int q0 = blockIdx.x * 256;

    const size_t rowbase = (size_t)b * LL;
    const uint32_t* pmb = pm + (size_t)b * LL * (LL/32);

    // ---- stage Q planes (persistent) ----------------------------------------
    #pragma unroll
    for (int p = 0; p < 4; p++) {
        int idx = p * 512 + tid;            // 0..2047 = 256 rows x 8 chunks
        int r   = idx >> 3;
        int ch  = (idx & 7) * 8;
        size_t src = (rowbase + q0 + r) * (size_t)D3 + h*64 + ch;
        cp_async16(&QstH[r*KV_PAD + ch], qh + src);
        cp_async16(&QstL[r*KV_PAD + ch], ql + src);
    }
    CP_COMMIT();

    // ---- KV pipeline --------------------------------------------------------
    const int kv_r = tid >> 3;              // 0..63
    const int kv_c = (tid & 7) * 8;         // bf16 offset

    auto load_kv = [&](int tile, int slot) {
        char* sb = smem_raw + slot * ASTAGE_BYTES;
        __nv_bfloat16* KsH = (__nv_bfloat16*)sb;
        __nv_bfloat16* KsL = (__nv_bfloat16*)(sb + 9216);
        __nv_bfloat16* VsH = (__nv_bfloat16*)(sb + 18432);
        __nv_bfloat16* VsL = (__nv_bfloat16*)(sb + 27648);
        const int k0 = tile * 64;
        size_t base = (rowbase + k0 + kv_r) * (size_t)D3 + h*64 + kv_c;
        cp_async16(&KsH[kv_r*KV_PAD + kv_c], qh + base + 1024);
        cp_async16(&KsL[kv_r*KV_PAD + kv_c], ql + base + 1024);
        cp_async16(&VsH[kv_r*KV_PAD + kv_c], qh + base + 2048);
        cp_async16(&VsL[kv_r*KV_PAD + kv_c], ql + base + 2048);
    };

    load_kv(0, 0); CP_COMMIT();
    load_kv(1, 1); CP_COMMIT();

    float oc[8][4];
    #pragma unroll
    for (int ni = 0; ni < 8; ni++)
        #pragma unroll
        for (int j = 0; j < 4; j++) oc[ni][j] = 0.0f;
    float mi0 = -1e30f, mi1 = -1e30f, li0 = 0.0f, li1 = 0.0f;

    const float cs = 0.18033688011112042f;  // log2(e)/sqrt(64)
    const int r0g = q0 + warp*16 + g;
    const int NT  = LL / 64;

    const int k_key = ((lane & 16) ? 8 : 0) + (lane & 7);
    const int k_dim = (lane & 8) ? 8 : 0;
    const int v_row = lane;
    const int q_row = warp*16 + (lane & 15);
    const int q_col = (lane >> 4) << 3;

    for (int tt = 0; tt < NT; tt++) {
        const int k0 = tt * 64;
        if (tt < NT - 1) CP_WAIT1(); else CP_WAIT0();
        __syncthreads();

        if (tt + 2 < NT) {
            load_kv(tt + 2, (tt + 2) % ASTAGES);
            CP_COMMIT();
        }

        char* sb = smem_raw + (tt % ASTAGES) * ASTAGE_BYTES;
        const __nv_bfloat16* KsH = (const __nv_bfloat16*)sb;
        const __nv_bfloat16* KsL = (const __nv_bfloat16*)(sb + 9216);
        const __nv_bfloat16* VsH = (const __nv_bfloat16*)(sb + 18432);
        const __nv_bfloat16* VsL = (const __nv_bfloat16*)(sb + 27648);

        // ---- S = Q @ K^T (warp tile 16x64) ----------------------------------
        float sc[8][4];
        #pragma unroll
        for (int ni = 0; ni < 8; ni++)
            #pragma unroll
            for (int j = 0; j < 4; j++) sc[ni][j] = 0.0f;

        #pragma unroll
        for (int kb = 0; kb < 4; kb++) {
            uint32_t aqH[4], aqL[4];
            ldsm_x4(aqH, su32(QstH + q_row*KV_PAD + kb*16 + q_col));
            ldsm_x4(aqL, su32(QstL + q_row*KV_PAD + kb*16 + q_col));
            #pragma unroll
            for (int njp = 0; njp < 4; njp++) {
                uint32_t kH[4], kL[4];
                ldsm_x4(kH, su32(KsH + (njp*16 + k_key)*KV_PAD + kb*16 + k_dim));
                ldsm_x4(kL, su32(KsL + (njp*16 + k_key)*KV_PAD + kb*16 + k_dim));
                mma_bf16(sc[2*njp],   aqH, kH[0], kH[1]);
                mma_bf16(sc[2*njp],   aqH, kL[0], kL[1]);
                mma_bf16(sc[2*njp],   aqL, kH[0], kH[1]);
                mma_bf16(sc[2*njp+1], aqH, kH[2], kH[3]);
                mma_bf16(sc[2*njp+1], aqH, kL[2], kL[3]);
                mma_bf16(sc[2*njp+1], aqL, kH[2], kH[3]);
            }
        }

        // ---- packed mask + online softmax (log2 domain) ---------------------
        const uint32_t* pr0 = pmb + (size_t)r0g * 64 + (k0 >> 5);
        const uint32_t* pr1 = pmb + (size_t)(r0g + 8) * 64 + (k0 >> 5);
        uint64_t m0 = (uint64_t)pr0[0] | ((uint64_t)pr0[1] << 32);
        uint64_t m1 = (uint64_t)pr1[0] | ((uint64_t)pr1[1] << 32);

        float tm0 = -1e30f, tm1 = -1e30f;
        uint32_t keep[8];
        #pragma unroll
        for (int ni = 0; ni < 8; ni++) {
            const int bit = ni*8 + 2*t;
            uint32_t p0 = (uint32_t)(m0 >> bit) & 3u;
            uint32_t p1 = (uint32_t)(m1 >> bit) & 3u;
            keep[ni] = p0 | (p1 << 2);
            sc[ni][0] = (p0 & 1) ? sc[ni][0]*cs : 0.0f;
            sc[ni][1] = (p0 & 2) ? sc[ni][1]*cs : 0.0f;
            sc[ni][2] = (p1 & 1) ? sc[ni][2]*cs : 0.0f;
            sc[ni][3] = (p1 & 2) ? sc[ni][3]*cs : 0.0f;
            tm0 = fmaxf(tm0, fmaxf(sc[ni][0], sc[ni][1]));
            tm1 = fmaxf(tm1, fmaxf(sc[ni][2], sc[ni][3]));
        }
        tm0 = fmaxf(tm0, __shfl_xor_sync(0xffffffffu, tm0, 1));
        tm0 = fmaxf(tm0, __shfl_xor_sync(0xffffffffu, tm0, 2));
        tm1 = fmaxf(tm1, __shfl_xor_sync(0xffffffffu, tm1, 1));
        tm1 = fmaxf(tm1, __shfl_xor_sync(0xffffffffu, tm1, 2));

        const float mn0 = fmaxf(mi0, tm0);
        const float mn1 = fmaxf(mi1, tm1);
        const float s0  = fexp2(mi0 - mn0);
        const float s1  = fexp2(mi1 - mn1);
        mi0 = mn0; mi1 = mn1;

        float sum0 = 0.0f, sum1 = 0.0f;
        #pragma unroll
        for (int ni = 0; ni < 8; ni++) {
            float e0 = fexp2(sc[ni][0] - mn0);
            float e1 = fexp2(sc[ni][1] - mn0);
            float e2 = fexp2(sc[ni][2] - mn1);
            float e3 = fexp2(sc[ni][3] - mn1);
            sum0 += e0 + e1;
            sum1 += e2 + e3;
            sc[ni][0] = (keep[ni] & 1) ? e0 : 0.0f;
            sc[ni][1] = (keep[ni] & 2) ? e1 : 0.0f;
            sc[ni][2] = (keep[ni] & 4) ? e2 : 0.0f;
            sc[ni][3] = (keep[ni] & 8) ? e3 : 0.0f;
        }
        sum0 += __shfl_xor_sync(0xffffffffu, sum0, 1);
        sum0 += __shfl_xor_sync(0xffffffffu, sum0, 2);
        sum1 += __shfl_xor_sync(0xffffffffu, sum1, 1);
        sum1 += __shfl_xor_sync(0xffffffffu, sum1, 2);
        li0 = li0 * s0 + sum0;
        li1 = li1 * s1 + sum1;

        #pragma unroll
        for (int ni = 0; ni < 8; ni++) {
            oc[ni][0] *= s0; oc[ni][1] *= s0;
            oc[ni][2] *= s1; oc[ni][3] *= s1;
        }

        // ---- O += P @ V (P repacked in registers) ---------------------------
        #pragma unroll
        for (int kb2 = 0; kb2 < 2; kb2++) {
            uint32_t apH[2][4], apL[2][4];
            #pragma unroll
            for (int kk = 0; kk < 2; kk++) {
                const int kbi = kb2*2 + kk;
                split_pair(sc[2*kbi][0],   sc[2*kbi][1],   apH[kk][0], apL[kk][0]);
                split_pair(sc[2*kbi][2],   sc[2*kbi][3],   apH[kk][1], apL[kk][1]);
                split_pair(sc[2*kbi+1][0], sc[2*kbi+1][1], apH[kk][2], apL[kk][2]);
                split_pair(sc[2*kbi+1][2], sc[2*kbi+1][3], apH[kk][3], apL[kk][3]);
            }
            #pragma unroll
            for (int nj = 0; nj < 8; nj++) {
                uint32_t vH[4], vL[4];
                ldsm_x4_t(vH, su32(VsH + (kb2*32 + v_row)*KV_PAD + nj*8));
                ldsm_x4_t(vL, su32(VsL + (kb2*32 + v_row)*KV_PAD + nj*8));
                mma_bf16(oc[nj], apH[0], vH[0], vH[1]);
                mma_bf16(oc[nj], apH[0], vL[0], vL[1]);
                mma_bf16(oc[nj], apL[0], vH[0], vH[1]);
                mma_bf16(oc[nj], apH[1], vH[2], vH[3]);
                mma_bf16(oc[nj], apH[1], vL[2], vL[3]);
                mma_bf16(oc[nj], apL[1], vH[2], vH[3]);
            }
        }
    }

    // ---- epilogue -----------------------------------------------------------
    const float inv0 = 1.0f / li0;
    const float inv1 = 1.0f / li1;
    #pragma unroll
    for (int ni = 0; ni < 8; ni++) {
        const int c = h*64 + ni*8 + 2*t;
        uint32_t hp, lp;
        split_pair(oc[ni][0]*inv0, oc[ni][1]*inv0, hp, lp);
        *(uint32_t*)&cth[(rowbase + r0g) * DD + c] = hp;
        *(uint32_t*)&ctl[(rowbase + r0g) * DD + c] = lp;
        split_pair(oc[ni][2]*inv1, oc[ni][3]*inv1, hp, lp);
        *(uint32_t*)&cth[(rowbase + r0g + 8) * DD + c] = hp;
        *(uint32_t*)&ctl[(rowbase + r0g + 8) * DD + c] = lp;
    }
}

// ---------------------------------------------------------------------------
extern "C" void kernel_launch(void* const* d_in, const int* in_sizes, int n_in,
                              void* d_out, int out_size)
{
    const float* inputs = (const float*)d_in[0];
    const int*   mask   = (const int*)  d_in[1];
    const float* W1     = (const float*)d_in[2];
    const float* b1     = (const float*)d_in[3];
    const float* W2     = (const float*)d_in[4];
    const float* b2     = (const float*)d_in[5];
    float* out = (float*)d_out;

    __nv_bfloat16 *xh, *xl, *w1h, *w1l, *w2h, *w2l, *qh, *ql, *ch, *cl;
    uint32_t* pmm;
    cudaGetSymbolAddress((void**)&xh,  g_xh);  cudaGetSymbolAddress((void**)&xl,  g_xl);
    cudaGetSymbolAddress((void**)&w1h, g_w1h); cudaGetSymbolAddress((void**)&w1l, g_w1l);
    cudaGetSymbolAddress((void**)&w2h, g_w2h); cudaGetSymbolAddress((void**)&w2l, g_w2l);
    cudaGetSymbolAddress((void**)&qh,  g_qh);  cudaGetSymbolAddress((void**)&ql,  g_ql);
    cudaGetSymbolAddress((void**)&ch,  g_ch);  cudaGetSymbolAddress((void**)&cl,  g_cl);
    cudaGetSymbolAddress((void**)&pmm, g_pm);

    cudaFuncSetAttribute(gemm_bf16x3<true>,
                         cudaFuncAttributeMaxDynamicSharedMemorySize, GEMM_SMEM_BYTES);
    cudaFuncSetAttribute(gemm_bf16x3<false>,
                         cudaFuncAttributeMaxDynamicSharedMemorySize, GEMM_SMEM_BYTES);
    cudaFuncSetAttribute(attn_bf16x3,
                         cudaFuncAttributeMaxDynamicSharedMemorySize, ATTN_SMEM_BYTES);

    // 0) pre-passes: splits + mask bit-pack
    {
        int nx = NROWS*DD/4, n1 = DD*D3/4, n2 = DD*DD/4;
        split_kernel<<<(nx+255)/256, 256>>>(inputs, xh, xl, nx);
        split_kernel<<<(n1+255)/256, 256>>>(W1, w1h, w1l, n1);
        split_kernel<<<(n2+255)/256, 256>>>(W2, w2h, w2l, n2);
        int nw = BB*LL*(LL/32);
        pack_mask_kernel<<<(nw+255)/256, 256>>>(mask, pmm, nw);
    }
    // 1) QKV projection -> qkv hi/lo planes
    {
        dim3 grid(D3/128, NROWS/128);
        gemm_bf16x3<true><<<grid, 512, GEMM_SMEM_BYTES>>>(
            xh, xl, w1h, w1l, b1, nullptr, qh, ql, NROWS, D3, DD);
    }
    // 2) fused masked attention -> ctx hi/lo planes
    {
        dim3 grid(LL/256, BB*HH);
        attn_bf16x3<<<grid, 512, ATTN_SMEM_BYTES>>>(qh, ql, pmm, ch, cl);
    }
    // 3) output projection -> fp32 out
    {
        dim3 grid(DD/128, NROWS/128);
        gemm_bf16x3<false><<<grid, 512, GEMM_SMEM_BYTES>>>(
            ch, cl, w2h, w2l, b2, out, nullptr, nullptr, NROWS, DD, DD);
    }
}